// round 9
// baseline (speedup 1.0000x reference)
#include <cuda_runtime.h>
#include <cuda_bf16.h>
#include <cstdint>
#include <math.h>

#define HN 64
#define HE 64
#define NNODE 50000
#define NEDGE 200000
#define NTRI  600000
#define CC 128
#define D3 320
#define EPSF 1e-5f
#define TILE_M 128
#define NT_TILES ((NTRI + TILE_M - 1) / TILE_M)   // 4688
#define NE_TILES ((NEDGE + TILE_M - 1) / TILE_M)  // 1563

// ---------------- scratch ----------------
__device__ float g_y2[(size_t)NEDGE * CC];
__device__ float g_y3[(size_t)NTRI * CC];
__device__ float g_g2[(size_t)NEDGE * HE];
__device__ float g_agg[(size_t)NEDGE * HE];
__device__ unsigned short g_wbh[128 * 320];   // W3 hi bf16, panelized+swizzled
__device__ unsigned short g_wbl[128 * 320];   // W3 lo bf16
__device__ unsigned short g_w2h[128 * 64];    // W2 hi bf16
__device__ unsigned short g_w2l[128 * 64];    // W2 lo bf16
__device__ unsigned short g_nodeh[(size_t)NNODE * 64];   // node bf16 hi rows
__device__ unsigned short g_nodel[(size_t)NNODE * 64];   // node bf16 lo rows
__device__ unsigned short g_edgeh[(size_t)NEDGE * 64];
__device__ unsigned short g_edgel[(size_t)NEDGE * 64];
__device__ float g_sumbuf[768];
__device__ float g_ab[768];

// ---------------- helpers ----------------
__device__ __forceinline__ float sigmoidf_(float x) { return 1.0f / (1.0f + __expf(-x)); }
__device__ __forceinline__ uint32_t smem_u32(const void* p) {
    uint32_t a;
    asm("{ .reg .u64 t; cvta.to.shared.u64 t, %1; cvt.u32.u64 %0, t; }" : "=r"(a) : "l"(p));
    return a;
}
__device__ __forceinline__ uint32_t bfpack(float f0, float f1) {   // f0 -> low half
    uint32_t r;
    asm("cvt.rn.bf16x2.f32 %0, %1, %2;" : "=r"(r) : "f"(f1), "f"(f0));
    return r;
}
__device__ __forceinline__ void cvt_pair(float f0, float f1, uint32_t& h, uint32_t& l) {
    h = bfpack(f0, f1);
    float r0 = f0 - __uint_as_float((h & 0xFFFFu) << 16);
    float r1 = f1 - __uint_as_float(h & 0xFFFF0000u);
    l = bfpack(r0, r1);
}
__device__ __forceinline__ void ldsm_x4(uint32_t addr, uint32_t* r) {
    asm volatile("ldmatrix.sync.aligned.m8n8.x4.shared.b16 {%0,%1,%2,%3}, [%4];"
        : "=r"(r[0]), "=r"(r[1]), "=r"(r[2]), "=r"(r[3]) : "r"(addr));
}
__device__ __forceinline__ void mma_bf16(float* c, const uint32_t* a, const uint32_t* b) {
    asm volatile("mma.sync.aligned.m16n8k16.row.col.f32.bf16.bf16.f32 "
        "{%0,%1,%2,%3}, {%4,%5,%6,%7}, {%8,%9}, {%0,%1,%2,%3};"
        : "+f"(c[0]), "+f"(c[1]), "+f"(c[2]), "+f"(c[3])
        : "r"(a[0]), "r"(a[1]), "r"(a[2]), "r"(a[3]), "r"(b[0]), "r"(b[1]));
}
__device__ __forceinline__ uint32_t a_addr(uint32_t base, int r0, int k0, int lane) {
    int row = r0 + (lane & 15);
    int kk = k0 + ((lane >> 4) << 3);
    return base + row * 128 + ((kk * 2) ^ ((row & 7) << 4));
}
__device__ __forceinline__ uint32_t b_addr(uint32_t base, int n0, int k0, int lane) {
    int row = n0 + (lane & 7) + ((lane >> 4) << 3);
    int kk = k0 + (((lane >> 3) & 1) << 3);
    return base + row * 128 + ((kk * 2) ^ ((row & 7) << 4));
}
__device__ __forceinline__ void cp16(uint32_t dst, const void* src, int sz) {
    asm volatile("cp.async.ca.shared.global [%0], [%1], 16, %2;"
                 :: "r"(dst), "l"(src), "r"(sz) : "memory");
}
#define CP_COMMIT() asm volatile("cp.async.commit_group;" ::: "memory")
#define CP_WAIT1()  asm volatile("cp.async.wait_group 1;" ::: "memory")

// c3 SMEM: W hi [0,81920), W lo [81920,163840), A bufs [163840, +65536)
#define SW_A 163840
#define SMEM_C3 (SW_A + 65536)   // 229376 B dynamic
// c2 SMEM: W2h [0,16KB), W2l [16KB,32KB), A bufs [32KB, 96KB)
#define SW2_A 32768
#define SMEM_C2 (SW2_A + 65536)  // 98304 B dynamic

// ============================================================================
__global__ void k_zero() {
    size_t i = (size_t)blockIdx.x * blockDim.x + threadIdx.x;
    size_t stride = (size_t)gridDim.x * blockDim.x;
    size_t n = (size_t)NEDGE * HE / 4;
    float4 z = make_float4(0.f, 0.f, 0.f, 0.f);
    float4* p4 = (float4*)g_agg;
    for (size_t p = i; p < n; p += stride) p4[p] = z;
    if (i < 768) g_sumbuf[i] = 0.0f;
}

// W3 bf16 hi/lo panelized swizzled images (panel p = k>>6)
__global__ void k_prepw(const float* __restrict__ W3) {
    int idx = blockIdx.x * 256 + threadIdx.x;
    if (idx >= 128 * 320) return;
    int n = idx / 320, k = idx - n * 320;
    float w = W3[idx];
    __nv_bfloat16 hb = __float2bfloat16_rn(w);
    __nv_bfloat16 lb = __float2bfloat16_rn(w - __bfloat162float(hb));
    int p = k >> 6, kk = k & 63;
    uint32_t byte = (uint32_t)p * 16384u + (uint32_t)n * 128u + (uint32_t)((kk * 2) ^ ((n & 7) << 4));
    g_wbh[byte >> 1] = __bfloat16_as_ushort(hb);
    g_wbl[byte >> 1] = __bfloat16_as_ushort(lb);
}
// W2 images (single K=64 panel)
__global__ void k_prepw2(const float* __restrict__ W2) {
    int idx = blockIdx.x * 256 + threadIdx.x;
    if (idx >= 128 * 64) return;
    int n = idx >> 6, k = idx & 63;
    float w = W2[idx];
    __nv_bfloat16 hb = __float2bfloat16_rn(w);
    __nv_bfloat16 lb = __float2bfloat16_rn(w - __bfloat162float(hb));
    uint32_t byte = (uint32_t)n * 128u + (uint32_t)((k * 2) ^ ((n & 7) << 4));
    g_w2h[byte >> 1] = __bfloat16_as_ushort(hb);
    g_w2l[byte >> 1] = __bfloat16_as_ushort(lb);
}
// node/edge bf16 hi/lo row images (plain row-major)
__global__ void __launch_bounds__(256) k_prepx(const float* __restrict__ node,
                                               const float* __restrict__ edge) {
    size_t i = (size_t)blockIdx.x * 256 + threadIdx.x;
    size_t stride = (size_t)gridDim.x * 256;
    const size_t nn = (size_t)NNODE * 16;
    const size_t ne = (size_t)NEDGE * 16;
    for (size_t p = i; p < nn + ne; p += stride) {
        float4 v = (p < nn) ? ((const float4*)node)[p] : ((const float4*)edge)[p - nn];
        uint32_t h0, l0, h1, l1;
        cvt_pair(v.x, v.y, h0, l0);
        cvt_pair(v.z, v.w, h1, l1);
        if (p < nn) {
            ((uint2*)g_nodeh)[p] = make_uint2(h0, h1);
            ((uint2*)g_nodel)[p] = make_uint2(l0, l1);
        } else {
            ((uint2*)g_edgeh)[p - nn] = make_uint2(h0, h1);
            ((uint2*)g_edgel)[p - nn] = make_uint2(l0, l1);
        }
    }
}

// ---------------- MMA panel bodies ----------------
// 16-warp variant: warp covers 32 rows x 32 cols, acc[2][4][4]
__device__ __forceinline__ void mma_panel16(uint32_t abase, uint32_t wbh, uint32_t wbl,
                                            int wm, int wn, int lane, float acc[2][4][4]) {
    uint32_t abl = abase + 16384;
#pragma unroll
    for (int ks = 0; ks < 4; ks++) {
        int k0 = ks * 16;
        uint32_t ah[2][4], al[2][4], bh[2][4], bl[2][4];
        ldsm_x4(a_addr(abase, wm * 32, k0, lane), ah[0]);
        ldsm_x4(a_addr(abase, wm * 32 + 16, k0, lane), ah[1]);
        ldsm_x4(a_addr(abl, wm * 32, k0, lane), al[0]);
        ldsm_x4(a_addr(abl, wm * 32 + 16, k0, lane), al[1]);
        ldsm_x4(b_addr(wbh, wn * 32, k0, lane), bh[0]);
        ldsm_x4(b_addr(wbh, wn * 32 + 16, k0, lane), bh[1]);
        ldsm_x4(b_addr(wbl, wn * 32, k0, lane), bl[0]);
        ldsm_x4(b_addr(wbl, wn * 32 + 16, k0, lane), bl[1]);
#pragma unroll
        for (int mt = 0; mt < 2; mt++)
#pragma unroll
            for (int g = 0; g < 2; g++) {
                mma_bf16(acc[mt][2 * g],     ah[mt], &bh[g][0]);
                mma_bf16(acc[mt][2 * g + 1], ah[mt], &bh[g][2]);
                mma_bf16(acc[mt][2 * g],     ah[mt], &bl[g][0]);
                mma_bf16(acc[mt][2 * g + 1], ah[mt], &bl[g][2]);
                mma_bf16(acc[mt][2 * g],     al[mt], &bh[g][0]);
                mma_bf16(acc[mt][2 * g + 1], al[mt], &bh[g][2]);
            }
    }
}
// 8-warp variant: warp covers 32 rows x 64 cols, acc[2][8][4]
__device__ __forceinline__ void mma_panel64(uint32_t abase, uint32_t wbh, uint32_t wbl,
                                            int wm, int wn, int lane, float acc[2][8][4]) {
    uint32_t abl = abase + 16384;
#pragma unroll
    for (int ks = 0; ks < 4; ks++) {
        int k0 = ks * 16;
        uint32_t ah[2][4], al[2][4];
        ldsm_x4(a_addr(abase, wm * 32, k0, lane), ah[0]);
        ldsm_x4(a_addr(abase, wm * 32 + 16, k0, lane), ah[1]);
        ldsm_x4(a_addr(abl, wm * 32, k0, lane), al[0]);
        ldsm_x4(a_addr(abl, wm * 32 + 16, k0, lane), al[1]);
        uint32_t bh[4][4], bl[4][4];
#pragma unroll
        for (int g = 0; g < 4; g++) {
            ldsm_x4(b_addr(wbh, wn * 64 + g * 16, k0, lane), bh[g]);
            ldsm_x4(b_addr(wbl, wn * 64 + g * 16, k0, lane), bl[g]);
        }
#pragma unroll
        for (int mt = 0; mt < 2; mt++)
#pragma unroll
            for (int g = 0; g < 4; g++) {
                mma_bf16(acc[mt][2 * g],     ah[mt], &bh[g][0]);
                mma_bf16(acc[mt][2 * g + 1], ah[mt], &bh[g][2]);
                mma_bf16(acc[mt][2 * g],     ah[mt], &bl[g][0]);
                mma_bf16(acc[mt][2 * g + 1], ah[mt], &bl[g][2]);
                mma_bf16(acc[mt][2 * g],     al[mt], &bh[g][0]);
                mma_bf16(acc[mt][2 * g + 1], al[mt], &bh[g][2]);
            }
    }
}

// ---------------- c3 async A-panel feed ----------------
__device__ __forceinline__ void issue_panel(const unsigned short* __restrict__ sh,
                                            const unsigned short* __restrict__ sl,
                                            const int* __restrict__ idx,
                                            int tbase, uint32_t abase, int tid) {
    int r = tid >> 2, q = tid & 3;
    int t = tbase + r;
    bool valid = (t < NTRI);
    int gi = valid ? idx[t] : 0;
    int sz = valid ? 16 : 0;
    const char* ph = (const char*)(sh + (size_t)gi * 64) + q * 32;
    const char* pl = (const char*)(sl + (size_t)gi * 64) + q * 32;
    int swm = (r & 7) << 4;
    uint32_t row = abase + (uint32_t)r * 128u;
    uint32_t o0 = row + (uint32_t)((q * 32) ^ swm);
    uint32_t o1 = row + (uint32_t)((q * 32 + 16) ^ swm);
    cp16(o0, ph, sz);
    cp16(o1, ph + 16, sz);
    cp16(o0 + 16384, pl, sz);
    cp16(o1 + 16384, pl + 16, sz);
}

// ---------------- c2 gather (product; stays register path) ----------------
__device__ __forceinline__ void gather2(const float* __restrict__ node,
                                        const int* __restrict__ vi,
                                        const int* __restrict__ vj,
                                        int tbase, int tid, float4* v) {
    int r = tid >> 1, h = tid & 1;
    int e = tbase + r;
    if (e < NEDGE) {
        const float4* a = (const float4*)(node + (size_t)vi[e] * 64) + h * 8;
        const float4* b = (const float4*)(node + (size_t)vj[e] * 64) + h * 8;
#pragma unroll
        for (int i = 0; i < 8; i++) {
            float4 x = a[i], y = b[i];
            v[i] = make_float4(x.x * y.x, x.y * y.y, x.z * y.z, x.w * y.w);
        }
    } else {
#pragma unroll
        for (int i = 0; i < 8; i++) v[i] = make_float4(0.f, 0.f, 0.f, 0.f);
    }
}
__device__ __forceinline__ void cvt_store2(const float4* v, char* buf, int tid) {
    int r = tid >> 1, h = tid & 1;
    int swm = (r & 7) << 4;
#pragma unroll
    for (int i = 0; i < 8; i++) {
        uint32_t h0, l0, h1, l1;
        cvt_pair(v[i].x, v[i].y, h0, l0);
        cvt_pair(v[i].z, v[i].w, h1, l1);
        int off = r * 128 + ((h * 64 + i * 8) ^ swm);
        *(uint2*)(buf + off) = make_uint2(h0, h1);
        *(uint2*)(buf + 16384 + off) = make_uint2(l0, l1);
    }
}

// ============================================================================
// K2: c3 linear via HMMA + cp.async A feed, 512 threads + fused y3 stats
// ============================================================================
__global__ void __launch_bounds__(512, 1) k_c3mm(const int* __restrict__ ii,
                                                 const int* __restrict__ ij,
                                                 const int* __restrict__ ik,
                                                 const int* __restrict__ iji,
                                                 const int* __restrict__ ikj) {
    extern __shared__ __align__(128) char smal[];
    __shared__ float sred[256];
    const uint32_t sbal = smem_u32(smal);
    const int tid = threadIdx.x, wid = tid >> 5, lane = tid & 31;
    const int wm = wid >> 2, wn = wid & 3;
    {
        const uint4* srch = (const uint4*)g_wbh;
        const uint4* srcl = (const uint4*)g_wbl;
        uint4* dsth = (uint4*)smal;
        uint4* dstl = (uint4*)(smal + 81920);
        for (int i = tid; i < 5120; i += 512) { dsth[i] = srch[i]; dstl[i] = srcl[i]; }
    }
    if (tid < 256) sred[tid] = 0.0f;
    __syncthreads();

    uint32_t bp = 0;
    issue_panel(g_nodeh, g_nodel, ii, blockIdx.x * TILE_M, sbal + SW_A, tid);
    CP_COMMIT();
    const int lr = lane >> 2, lq = lane & 3;

    for (int tile = blockIdx.x; tile < NT_TILES; tile += gridDim.x) {
        const int tbase = tile * TILE_M;
        float acc[2][4][4];
#pragma unroll
        for (int mt = 0; mt < 2; mt++)
#pragma unroll
            for (int nt = 0; nt < 4; nt++)
#pragma unroll
                for (int u = 0; u < 4; u++) acc[mt][nt][u] = 0.0f;

        uint32_t A0 = sbal + SW_A + bp;
        uint32_t A1 = sbal + SW_A + (bp ^ 32768u);

        issue_panel(g_nodeh, g_nodel, ij, tbase, A1, tid); CP_COMMIT();
        CP_WAIT1(); __syncthreads();
        mma_panel16(A0, sbal, sbal + 81920u, wm, wn, lane, acc);
        __syncthreads();

        issue_panel(g_nodeh, g_nodel, ik, tbase, A0, tid); CP_COMMIT();
        CP_WAIT1(); __syncthreads();
        mma_panel16(A1, sbal + 16384u, sbal + 98304u, wm, wn, lane, acc);
        __syncthreads();

        issue_panel(g_edgeh, g_edgel, iji, tbase, A1, tid); CP_COMMIT();
        CP_WAIT1(); __syncthreads();
        mma_panel16(A0, sbal + 32768u, sbal + 114688u, wm, wn, lane, acc);
        __syncthreads();

        issue_panel(g_edgeh, g_edgel, ikj, tbase, A0, tid); CP_COMMIT();
        CP_WAIT1(); __syncthreads();
        mma_panel16(A1, sbal + 49152u, sbal + 131072u, wm, wn, lane, acc);
        __syncthreads();

        issue_panel(g_nodeh, g_nodel, ii, (tile + gridDim.x) * TILE_M, A1, tid); CP_COMMIT();
        CP_WAIT1(); __syncthreads();
        mma_panel16(A0, sbal + 65536u, sbal + 147456u, wm, wn, lane, acc);

        // epilogue: y3 stores + fused column stats
#pragma unroll
        for (int mt = 0; mt < 2; mt++) {
            int gr = tbase + wm * 32 + mt * 16 + lr;
#pragma unroll
            for (int nt = 0; nt < 4; nt++) {
                int col = wn * 32 + nt * 8 + lq * 2;
                if (gr < NTRI)
                    *(float2*)&g_y3[(size_t)gr * CC + col] = make_float2(acc[mt][nt][0], acc[mt][nt][1]);
                if (gr + 8 < NTRI)
                    *(float2*)&g_y3[(size_t)(gr + 8) * CC + col] = make_float2(acc[mt][nt][2], acc[mt][nt][3]);
            }
        }
        float sv[8], qv[8];
#pragma unroll
        for (int nt = 0; nt < 4; nt++)
#pragma unroll
            for (int j = 0; j < 2; j++) {
                float a0 = acc[0][nt][j], a1 = acc[0][nt][j + 2];
                float a2 = acc[1][nt][j], a3 = acc[1][nt][j + 2];
                sv[nt * 2 + j] = a0 + a1 + a2 + a3;
                qv[nt * 2 + j] = a0 * a0 + a1 * a1 + a2 * a2 + a3 * a3;
            }
#pragma unroll
        for (int i = 0; i < 8; i++) {
#pragma unroll
            for (int m = 4; m < 32; m <<= 1) {
                sv[i] += __shfl_xor_sync(0xffffffff, sv[i], m);
                qv[i] += __shfl_xor_sync(0xffffffff, qv[i], m);
            }
        }
        if (lane < 4) {
#pragma unroll
            for (int i = 0; i < 8; i++) {
                int col = wn * 32 + (i >> 1) * 8 + lane * 2 + (i & 1);
                atomicAdd(&sred[col], sv[i]);
                atomicAdd(&sred[128 + col], qv[i]);
            }
        }
        __syncthreads();
        bp ^= 32768u;
    }
    __syncthreads();
    if (tid < 256) atomicAdd(&g_sumbuf[256 + tid], sred[tid]);
}

// ============================================================================
// K1: c2 linear via HMMA (K=64, 1 panel, cross-tile double buffer) + y2 stats
// ============================================================================
__global__ void __launch_bounds__(256, 1) k_c2mm(const float* __restrict__ node,
                                                 const int* __restrict__ vi,
                                                 const int* __restrict__ vj) {
    extern __shared__ __align__(128) char smal[];
    __shared__ float sred[256];
    const uint32_t sbal = smem_u32(smal);
    const int tid = threadIdx.x, wid = tid >> 5, lane = tid & 31;
    const int wm = wid >> 1, wn = wid & 1;
    {
        const uint4* srch = (const uint4*)g_w2h;
        const uint4* srcl = (const uint4*)g_w2l;
        uint4* dsth = (uint4*)smal;
        uint4* dstl = (uint4*)(smal + 16384);
        for (int i = tid; i < 1024; i += 256) { dsth[i] = srch[i]; dstl[i] = srcl[i]; }
    }
    sred[tid] = 0.0f;

    float4 v[8];
    int tile = blockIdx.x;
    if (tile < NE_TILES) {
        gather2(node, vi, vj, tile * TILE_M, tid, v);
        cvt_store2(v, smal + SW2_A, tid);
    }
    __syncthreads();
    uint32_t parOff = 0;
    const int lr = lane >> 2, lq = lane & 3;

    for (; tile < NE_TILES; tile += gridDim.x) {
        const int tbase = tile * TILE_M;
        float acc[2][8][4];
#pragma unroll
        for (int mt = 0; mt < 2; mt++)
#pragma unroll
            for (int nt = 0; nt < 8; nt++)
#pragma unroll
                for (int u = 0; u < 4; u++) acc[mt][nt][u] = 0.0f;

        int ntile = tile + gridDim.x;
        if (ntile < NE_TILES) gather2(node, vi, vj, ntile * TILE_M, tid, v);
        mma_panel64(sbal + SW2_A + parOff, sbal, sbal + 16384u, wm, wn, lane, acc);
        if (ntile < NE_TILES) cvt_store2(v, smal + SW2_A + (parOff ^ 32768u), tid);

#pragma unroll
        for (int mt = 0; mt < 2; mt++) {
            int gr = tbase + wm * 32 + mt * 16 + lr;
#pragma unroll
            for (int nt = 0; nt < 8; nt++) {
                int col = wn * 64 + nt * 8 + lq * 2;
                if (gr < NEDGE)
                    *(float2*)&g_y2[(size_t)gr * CC + col] = make_float2(acc[mt][nt][0], acc[mt][nt][1]);
                if (gr + 8 < NEDGE)
                    *(float2*)&g_y2[(size_t)(gr + 8) * CC + col] = make_float2(acc[mt][nt][2], acc[mt][nt][3]);
            }
        }
        float sv[16], qv[16];
#pragma unroll
        for (int nt = 0; nt < 8; nt++)
#pragma unroll
            for (int j = 0; j < 2; j++) {
                float a0 = acc[0][nt][j], a1 = acc[0][nt][j + 2];
                float a2 = acc[1][nt][j], a3 = acc[1][nt][j + 2];
                sv[nt * 2 + j] = a0 + a1 + a2 + a3;
                qv[nt * 2 + j] = a0 * a0 + a1 * a1 + a2 * a2 + a3 * a3;
            }
#pragma unroll
        for (int i = 0; i < 16; i++) {
#pragma unroll
            for (int m = 4; m < 32; m <<= 1) {
                sv[i] += __shfl_xor_sync(0xffffffff, sv[i], m);
                qv[i] += __shfl_xor_sync(0xffffffff, qv[i], m);
            }
        }
        if (lane < 4) {
#pragma unroll
            for (int i = 0; i < 16; i++) {
                int col = wn * 64 + (i >> 1) * 8 + lane * 2 + (i & 1);
                atomicAdd(&sred[col], sv[i]);
                atomicAdd(&sred[128 + col], qv[i]);
            }
        }
        __syncthreads();
        parOff ^= 32768u;
    }
    __syncthreads();
    atomicAdd(&g_sumbuf[tid], sred[tid]);
}

// ============================================================================
__global__ void k_stats1(const float* __restrict__ gc2, const float* __restrict__ bc2,
                         const float* __restrict__ gc3, const float* __restrict__ bc3) {
    int tid = threadIdx.x;  // 256
    if (tid < 128) {
        float mean = g_sumbuf[tid] * (1.0f / NEDGE);
        float var  = g_sumbuf[128 + tid] * (1.0f / NEDGE) - mean * mean;
        float a = gc2[tid] * rsqrtf(var + EPSF);
        g_ab[tid] = a;
        g_ab[128 + tid] = bc2[tid] - mean * a;
    } else {
        int c = tid - 128;
        float mean = g_sumbuf[256 + c] * (1.0f / NTRI);
        float var  = g_sumbuf[384 + c] * (1.0f / NTRI) - mean * mean;
        float a = gc3[c] * rsqrtf(var + EPSF);
        g_ab[256 + c] = a;
        g_ab[384 + c] = bc3[c] - mean * a;
    }
}

// ============================================================================
__global__ void __launch_bounds__(256) k_c2act() {
    __shared__ float sred[128];
    int tid = threadIdx.x;
    if (tid < 128) sred[tid] = 0.0f;
    __syncthreads();
    size_t i0 = (size_t)blockIdx.x * 256 + tid;
    int c = (int)(i0 & 15) * 4;
    float4 af = *(const float4*)&g_ab[c];
    float4 bf = *(const float4*)&g_ab[128 + c];
    float4 ac = *(const float4*)&g_ab[64 + c];
    float4 bc = *(const float4*)&g_ab[192 + c];
    float s[4] = {0, 0, 0, 0}, q[4] = {0, 0, 0, 0};
    size_t stride = (size_t)gridDim.x * 256;
    size_t n = (size_t)NEDGE * 16;
    for (size_t idx = i0; idx < n; idx += stride) {
        size_t e = idx >> 4;
        float4 yf = *(const float4*)&g_y2[(e << 7) + c];
        float4 yc = *(const float4*)&g_y2[(e << 7) + 64 + c];
        float4 g;
        g.x = sigmoidf_(yf.x * af.x + bf.x) * tanhf(yc.x * ac.x + bc.x);
        g.y = sigmoidf_(yf.y * af.y + bf.y) * tanhf(yc.y * ac.y + bc.y);
        g.z = sigmoidf_(yf.z * af.z + bf.z) * tanhf(yc.z * ac.z + bc.z);
        g.w = sigmoidf_(yf.w * af.w + bf.w) * tanhf(yc.w * ac.w + bc.w);
        *(float4*)&g_g2[idx << 2] = g;
        s[0] += g.x; s[1] += g.y; s[2] += g.z; s[3] += g.w;
        q[0] += g.x * g.x; q[1] += g.y * g.y; q[2] += g.z * g.z; q[3] += g.w * g.w;
    }
#pragma unroll
    for (int u = 0; u < 4; u++) {
        atomicAdd(&sred[c + u], s[u]);
        atomicAdd(&sred[64 + c + u], q[u]);
    }
    __syncthreads();
    if (tid < 128) atomicAdd(&g_sumbuf[512 + tid], sred[tid]);
}

// ============================================================================
__global__ void __launch_bounds__(256) k_c3act(const int* __restrict__ iji) {
    size_t i0 = (size_t)blockIdx.x * 256 + threadIdx.x;
    int c = (int)(i0 & 15) * 4;
    float4 af = *(const float4*)&g_ab[256 + c];
    float4 bf = *(const float4*)&g_ab[384 + c];
    float4 ac = *(const float4*)&g_ab[320 + c];
    float4 bc = *(const float4*)&g_ab[448 + c];
    size_t stride = (size_t)gridDim.x * 256;
    size_t n = (size_t)NTRI * 16;
    for (size_t idx = i0; idx < n; idx += stride) {
        size_t t = idx >> 4;
        float4 yf = *(const float4*)&g_y3[(t << 7) + c];
        float4 yc = *(const float4*)&g_y3[(t << 7) + 64 + c];
        float m0 = sigmoidf_(yf.x * af.x + bf.x) * tanhf(yc.x * ac.x + bc.x);
        float m1 = sigmoidf_(yf.y * af.y + bf.y) * tanhf(yc.y * ac.y + bc.y);
        float m2 = sigmoidf_(yf.z * af.z + bf.z) * tanhf(yc.z * ac.z + bc.z);
        float m3 = sigmoidf_(yf.w * af.w + bf.w) * tanhf(yc.w * ac.w + bc.w);
        float* dst = g_agg + ((size_t)iji[t] << 6) + c;
        asm volatile("red.global.v4.f32.add [%0], {%1, %2, %3, %4};"
                     :: "l"(dst), "f"(m0), "f"(m1), "f"(m2), "f"(m3) : "memory");
    }
}

// ============================================================================
__global__ void __launch_bounds__(256) k_aggstats() {
    __shared__ float sred[128];
    int tid = threadIdx.x;
    if (tid < 128) sred[tid] = 0.0f;
    __syncthreads();
    size_t i0 = (size_t)blockIdx.x * 256 + tid;
    int c = (int)(i0 & 15) * 4;
    float s[4] = {0, 0, 0, 0}, q[4] = {0, 0, 0, 0};
    size_t stride = (size_t)gridDim.x * 256;
    size_t n = (size_t)NEDGE * 16;
    for (size_t idx = i0; idx < n; idx += stride) {
        float4 vv = *(const float4*)&g_agg[idx << 2];
        s[0] += vv.x; s[1] += vv.y; s[2] += vv.z; s[3] += vv.w;
        q[0] += vv.x * vv.x; q[1] += vv.y * vv.y; q[2] += vv.z * vv.z; q[3] += vv.w * vv.w;
    }
#pragma unroll
    for (int u = 0; u < 4; u++) {
        atomicAdd(&sred[c + u], s[u]);
        atomicAdd(&sred[64 + c + u], q[u]);
    }
    __syncthreads();
    if (tid < 128) atomicAdd(&g_sumbuf[640 + tid], sred[tid]);
}

// ============================================================================
__global__ void k_stats2(const float* __restrict__ g22, const float* __restrict__ b22,
                         const float* __restrict__ g32, const float* __restrict__ b32) {
    int tid = threadIdx.x;  // 128
    if (tid < 64) {
        float mean = g_sumbuf[512 + tid] * (1.0f / NEDGE);
        float var  = g_sumbuf[576 + tid] * (1.0f / NEDGE) - mean * mean;
        float a = g22[tid] * rsqrtf(var + EPSF);
        g_ab[512 + tid] = a;
        g_ab[576 + tid] = b22[tid] - mean * a;
    } else {
        int c = tid - 64;
        float mean = g_sumbuf[640 + c] * (1.0f / NEDGE);
        float var  = g_sumbuf[704 + c] * (1.0f / NEDGE) - mean * mean;
        float a = g32[c] * rsqrtf(var + EPSF);
        g_ab[640 + c] = a;
        g_ab[704 + c] = b32[c] - mean * a;
    }
}

// ============================================================================
__global__ void __launch_bounds__(256) k_out(const float* __restrict__ edge,
                                             float* __restrict__ out) {
    size_t i0 = (size_t)blockIdx.x * 256 + threadIdx.x;
    int c = (int)(i0 & 15) * 4;
    float4 a2 = *(const float4*)&g_ab[512 + c];
    float4 b2v = *(const float4*)&g_ab[576 + c];
    float4 a3 = *(const float4*)&g_ab[640 + c];
    float4 b3v = *(const float4*)&g_ab[704 + c];
    size_t stride = (size_t)gridDim.x * 256;
    size_t n = (size_t)NEDGE * 16;
    for (size_t idx = i0; idx < n; idx += stride) {
        float4 e = *(const float4*)&edge[idx << 2];
        float4 g = *(const float4*)&g_g2[idx << 2];
        float4 a = *(const float4*)&g_agg[idx << 2];
        float4 o;
        o.x = tanhf(e.x + g.x * a2.x + b2v.x + a.x * a3.x + b3v.x);
        o.y = tanhf(e.y + g.y * a2.y + b2v.y + a.y * a3.y + b3v.y);
        o.z = tanhf(e.z + g.z * a2.z + b2v.z + a.z * a3.z + b3v.z);
        o.w = tanhf(e.w + g.w * a2.w + b2v.w + a.w * a3.w + b3v.w);
        *(float4*)&out[idx << 2] = o;
    }
}

// ============================================================================
extern "C" void kernel_launch(void* const* d_in, const int* in_sizes, int n_in,
                              void* d_out, int out_size) {
    const float* node = (const float*)d_in[0];
    const float* edge = (const float*)d_in[1];
    const int* vi     = (const int*)d_in[2];
    const int* vj     = (const int*)d_in[3];
    const int* idx_i  = (const int*)d_in[4];
    const int* idx_j  = (const int*)d_in[5];
    const int* idx_k  = (const int*)d_in[6];
    const int* idx_ji = (const int*)d_in[7];
    const int* idx_kj = (const int*)d_in[8];
    const float* W2   = (const float*)d_in[9];
    const float* W3   = (const float*)d_in[11];
    const float* gc2  = (const float*)d_in[13];
    const float* bc2  = (const float*)d_in[14];
    const float* gc3  = (const float*)d_in[15];
    const float* bc3  = (const float*)d_in[16];
    const float* g22  = (const float*)d_in[17];
    const float* b22  = (const float*)d_in[18];
    const float* g32  = (const float*)d_in[19];
    const float* b32  = (const float*)d_in[20];
    float* out = (float*)d_out;

    cudaFuncSetAttribute(k_c2mm, cudaFuncAttributeMaxDynamicSharedMemorySize, SMEM_C2);
    cudaFuncSetAttribute(k_c3mm, cudaFuncAttributeMaxDynamicSharedMemorySize, SMEM_C3);

    k_zero<<<1024, 256>>>();
    k_prepw<<<160, 256>>>(W3);
    k_prepx<<<2048, 256>>>(node, edge);
    k_c3mm<<<148, 512, SMEM_C3>>>(idx_i, idx_j, idx_k, idx_ji, idx_kj);
    k_prepw2<<<32, 256>>>(W2);
    k_c2mm<<<148, 256, SMEM_C2>>>(node, vi, vj);
    k_stats1<<<1, 256>>>(gc2, bc2, gc3, bc3);
    k_c2act<<<512, 256>>>();
    k_c3act<<<2048, 256>>>(idx_ji);
    k_aggstats<<<512, 256>>>();
    k_stats2<<<1, 128>>>(g22, b22, g32, b32);
    k_out<<<512, 256>>>(edge, out);
}

// round 10
// speedup vs baseline: 1.1004x; 1.1004x over previous
#include <cuda_runtime.h>
#include <cuda_bf16.h>
#include <cstdint>
#include <math.h>

#define HN 64
#define HE 64
#define NNODE 50000
#define NEDGE 200000
#define NTRI  600000
#define CC 128
#define D3 320
#define EPSF 1e-5f
#define TILE_M 128
#define NT_TILES ((NTRI + TILE_M - 1) / TILE_M)   // 4688
#define NE_TILES ((NEDGE + TILE_M - 1) / TILE_M)  // 1563

// ---------------- scratch ----------------
__device__ float g_y2[(size_t)NEDGE * CC];
__device__ float g_y3[(size_t)NTRI * CC];
__device__ float g_g2[(size_t)NEDGE * HE];
__device__ float g_agg[(size_t)NEDGE * HE];
__device__ unsigned short g_wbh[128 * 320];     // W3 hi bf16, panelized+swizzled
__device__ unsigned short g_wblf[40960];        // W3 lo bf16, FRAGMENT-major
__device__ unsigned short g_w2h[128 * 64];      // W2 hi bf16
__device__ unsigned short g_w2l[128 * 64];      // W2 lo bf16
__device__ unsigned short g_nodeh[(size_t)NNODE * 64];
__device__ unsigned short g_nodel[(size_t)NNODE * 64];
__device__ unsigned short g_edgeh[(size_t)NEDGE * 64];
__device__ unsigned short g_edgel[(size_t)NEDGE * 64];
__device__ float g_sumbuf[768];
__device__ float g_ab[768];

// ---------------- helpers ----------------
__device__ __forceinline__ float sigmoidf_(float x) { return 1.0f / (1.0f + __expf(-x)); }
__device__ __forceinline__ uint32_t smem_u32(const void* p) {
    uint32_t a;
    asm("{ .reg .u64 t; cvta.to.shared.u64 t, %1; cvt.u32.u64 %0, t; }" : "=r"(a) : "l"(p));
    return a;
}
__device__ __forceinline__ uint32_t bfpack(float f0, float f1) {   // f0 -> low half
    uint32_t r;
    asm("cvt.rn.bf16x2.f32 %0, %1, %2;" : "=r"(r) : "f"(f1), "f"(f0));
    return r;
}
__device__ __forceinline__ void cvt_pair(float f0, float f1, uint32_t& h, uint32_t& l) {
    h = bfpack(f0, f1);
    float r0 = f0 - __uint_as_float((h & 0xFFFFu) << 16);
    float r1 = f1 - __uint_as_float(h & 0xFFFF0000u);
    l = bfpack(r0, r1);
}
__device__ __forceinline__ void ldsm_x4(uint32_t addr, uint32_t* r) {
    asm volatile("ldmatrix.sync.aligned.m8n8.x4.shared.b16 {%0,%1,%2,%3}, [%4];"
        : "=r"(r[0]), "=r"(r[1]), "=r"(r[2]), "=r"(r[3]) : "r"(addr));
}
__device__ __forceinline__ void mma_bf16(float* c, const uint32_t* a, const uint32_t* b) {
    asm volatile("mma.sync.aligned.m16n8k16.row.col.f32.bf16.bf16.f32 "
        "{%0,%1,%2,%3}, {%4,%5,%6,%7}, {%8,%9}, {%0,%1,%2,%3};"
        : "+f"(c[0]), "+f"(c[1]), "+f"(c[2]), "+f"(c[3])
        : "r"(a[0]), "r"(a[1]), "r"(a[2]), "r"(a[3]), "r"(b[0]), "r"(b[1]));
}
__device__ __forceinline__ uint32_t a_addr(uint32_t base, int r0, int k0, int lane) {
    int row = r0 + (lane & 15);
    int kk = k0 + ((lane >> 4) << 3);
    return base + row * 128 + ((kk * 2) ^ ((row & 7) << 4));
}
__device__ __forceinline__ uint32_t b_addr(uint32_t base, int n0, int k0, int lane) {
    int row = n0 + (lane & 7) + ((lane >> 4) << 3);
    int kk = k0 + (((lane >> 3) & 1) << 3);
    return base + row * 128 + ((kk * 2) ^ ((row & 7) << 4));
}
__device__ __forceinline__ void cp16(uint32_t dst, const void* src, int sz) {
    asm volatile("cp.async.ca.shared.global [%0], [%1], 16, %2;"
                 :: "r"(dst), "l"(src), "r"(sz) : "memory");
}
#define CP_COMMIT() asm volatile("cp.async.commit_group;" ::: "memory")
#define CP_WAIT1()  asm volatile("cp.async.wait_group 1;" ::: "memory")

// c3 SMEM: W hi panels [0,81920), A bufs x3 [81920, 180224)
#define SW_C3A 81920
#define SMEM_C3 (SW_C3A + 3 * 32768)   // 180224 B
// c2 SMEM: W2h [0,16K), W2l [16K,32K), A bufs x2 [32K, 96K)
#define SW2_A 32768
#define SMEM_C2 (SW2_A + 65536)        // 98304 B

// ============================================================================
__global__ void k_zero() {
    size_t i = (size_t)blockIdx.x * blockDim.x + threadIdx.x;
    size_t stride = (size_t)gridDim.x * blockDim.x;
    size_t n = (size_t)NEDGE * HE / 4;
    float4 z = make_float4(0.f, 0.f, 0.f, 0.f);
    float4* p4 = (float4*)g_agg;
    for (size_t p = i; p < n; p += stride) p4[p] = z;
    if (i < 768) g_sumbuf[i] = 0.0f;
}

// W3: hi -> panelized swizzled smem image; lo -> fragment-major gmem image
__global__ void k_prepw(const float* __restrict__ W3) {
    int idx = blockIdx.x * 256 + threadIdx.x;
    if (idx >= 128 * 320) return;
    int n = idx / 320, k = idx - n * 320;
    float w = W3[idx];
    __nv_bfloat16 hb = __float2bfloat16_rn(w);
    __nv_bfloat16 lb = __float2bfloat16_rn(w - __bfloat162float(hb));
    int p = k >> 6, kk = k & 63;
    uint32_t byte = (uint32_t)p * 16384u + (uint32_t)n * 128u + (uint32_t)((kk * 2) ^ ((n & 7) << 4));
    g_wbh[byte >> 1] = __bfloat16_as_ushort(hb);
    // fragment-major lo: frag group = p*64 + ks*16 + ng; lane holds n=ng*8+t/4,
    // k = ks*16 + (t%4)*2 + reg*8 + elem
    int ks = kk >> 4, k16 = kk & 15;
    int ng = n >> 3, nn = n & 7;
    int lane = nn * 4 + ((k16 & 7) >> 1);
    int reg = k16 >> 3, elem = k16 & 1;
    int uidx = (p * 64 + ks * 16 + ng) * 64 + lane * 2 + reg;
    g_wblf[uidx * 2 + elem] = __bfloat16_as_ushort(lb);
}
// W2 images (single K=64 panel, hi+lo both swizzled smem-style)
__global__ void k_prepw2(const float* __restrict__ W2) {
    int idx = blockIdx.x * 256 + threadIdx.x;
    if (idx >= 128 * 64) return;
    int n = idx >> 6, k = idx & 63;
    float w = W2[idx];
    __nv_bfloat16 hb = __float2bfloat16_rn(w);
    __nv_bfloat16 lb = __float2bfloat16_rn(w - __bfloat162float(hb));
    uint32_t byte = (uint32_t)n * 128u + (uint32_t)((k * 2) ^ ((n & 7) << 4));
    g_w2h[byte >> 1] = __bfloat16_as_ushort(hb);
    g_w2l[byte >> 1] = __bfloat16_as_ushort(lb);
}
// node/edge bf16 hi/lo row images
__global__ void __launch_bounds__(256) k_prepx(const float* __restrict__ node,
                                               const float* __restrict__ edge) {
    size_t i = (size_t)blockIdx.x * 256 + threadIdx.x;
    size_t stride = (size_t)gridDim.x * 256;
    const size_t nn = (size_t)NNODE * 16;
    const size_t ne = (size_t)NEDGE * 16;
    for (size_t p = i; p < nn + ne; p += stride) {
        float4 v = (p < nn) ? ((const float4*)node)[p] : ((const float4*)edge)[p - nn];
        uint32_t h0, l0, h1, l1;
        cvt_pair(v.x, v.y, h0, l0);
        cvt_pair(v.z, v.w, h1, l1);
        if (p < nn) {
            ((uint2*)g_nodeh)[p] = make_uint2(h0, h1);
            ((uint2*)g_nodel)[p] = make_uint2(l0, l1);
        } else {
            ((uint2*)g_edgeh)[p - nn] = make_uint2(h0, h1);
            ((uint2*)g_edgel)[p - nn] = make_uint2(l0, l1);
        }
    }
}

// ---------------- MMA panel bodies ----------------
// c3 variant: A hi/lo + W-hi from smem (ldsm), W-lo frags via LDG (pipelined)
__device__ __forceinline__ void mma_panelL(uint32_t abase, uint32_t whb, int p,
                                           int wn, int wm, int lane, float acc[2][4][4]) {
    uint32_t abl = abase + 16384;
    const uint2* wlf = (const uint2*)g_wblf;
    const int fb = p * 64;
    uint2 blf[4], nblf[4];
#pragma unroll
    for (int g = 0; g < 4; g++) blf[g] = wlf[(fb + wn * 4 + g) * 32 + lane];
#pragma unroll
    for (int ks = 0; ks < 4; ks++) {
        if (ks < 3) {
#pragma unroll
            for (int g = 0; g < 4; g++)
                nblf[g] = wlf[(fb + (ks + 1) * 16 + wn * 4 + g) * 32 + lane];
        }
        int k0 = ks * 16;
        uint32_t ah[2][4], al[2][4], bh[2][4];
        ldsm_x4(a_addr(abase, wm * 32, k0, lane), ah[0]);
        ldsm_x4(a_addr(abase, wm * 32 + 16, k0, lane), ah[1]);
        ldsm_x4(a_addr(abl, wm * 32, k0, lane), al[0]);
        ldsm_x4(a_addr(abl, wm * 32 + 16, k0, lane), al[1]);
        ldsm_x4(b_addr(whb, wn * 32, k0, lane), bh[0]);
        ldsm_x4(b_addr(whb, wn * 32 + 16, k0, lane), bh[1]);
#pragma unroll
        for (int mt = 0; mt < 2; mt++) {
#pragma unroll
            for (int g = 0; g < 2; g++) {
                mma_bf16(acc[mt][2 * g],     ah[mt], &bh[g][0]);
                mma_bf16(acc[mt][2 * g + 1], ah[mt], &bh[g][2]);
                mma_bf16(acc[mt][2 * g],     al[mt], &bh[g][0]);
                mma_bf16(acc[mt][2 * g + 1], al[mt], &bh[g][2]);
            }
#pragma unroll
            for (int g = 0; g < 4; g++)
                mma_bf16(acc[mt][g], ah[mt], (const uint32_t*)&blf[g]);
        }
        if (ks < 3) {
#pragma unroll
            for (int g = 0; g < 4; g++) blf[g] = nblf[g];
        }
    }
}
// c2 variant: hi/lo both in smem (16-warp, 32x32 tiles)
__device__ __forceinline__ void mma_panel16(uint32_t abase, uint32_t wbh, uint32_t wbl,
                                            int wm, int wn, int lane, float acc[2][4][4]) {
    uint32_t abl = abase + 16384;
#pragma unroll
    for (int ks = 0; ks < 4; ks++) {
        int k0 = ks * 16;
        uint32_t ah[2][4], al[2][4], bh[2][4], bl[2][4];
        ldsm_x4(a_addr(abase, wm * 32, k0, lane), ah[0]);
        ldsm_x4(a_addr(abase, wm * 32 + 16, k0, lane), ah[1]);
        ldsm_x4(a_addr(abl, wm * 32, k0, lane), al[0]);
        ldsm_x4(a_addr(abl, wm * 32 + 16, k0, lane), al[1]);
        ldsm_x4(b_addr(wbh, wn * 32, k0, lane), bh[0]);
        ldsm_x4(b_addr(wbh, wn * 32 + 16, k0, lane), bh[1]);
        ldsm_x4(b_addr(wbl, wn * 32, k0, lane), bl[0]);
        ldsm_x4(b_addr(wbl, wn * 32 + 16, k0, lane), bl[1]);
#pragma unroll
        for (int mt = 0; mt < 2; mt++)
#pragma unroll
            for (int g = 0; g < 2; g++) {
                mma_bf16(acc[mt][2 * g],     ah[mt], &bh[g][0]);
                mma_bf16(acc[mt][2 * g + 1], ah[mt], &bh[g][2]);
                mma_bf16(acc[mt][2 * g],     ah[mt], &bl[g][0]);
                mma_bf16(acc[mt][2 * g + 1], ah[mt], &bl[g][2]);
                mma_bf16(acc[mt][2 * g],     al[mt], &bh[g][0]);
                mma_bf16(acc[mt][2 * g + 1], al[mt], &bh[g][2]);
            }
    }
}

// ---------------- c3 async A-panel feed ----------------
__device__ __forceinline__ void issue_panel(const unsigned short* __restrict__ sh,
                                            const unsigned short* __restrict__ sl,
                                            const int* __restrict__ idx,
                                            int tbase, uint32_t abase, int tid) {
    int r = tid >> 2, q = tid & 3;
    int t = tbase + r;
    bool valid = (t < NTRI);
    int gi = valid ? idx[t] : 0;
    int sz = valid ? 16 : 0;
    const char* ph = (const char*)(sh + (size_t)gi * 64) + q * 32;
    const char* pl = (const char*)(sl + (size_t)gi * 64) + q * 32;
    int swm = (r & 7) << 4;
    uint32_t row = abase + (uint32_t)r * 128u;
    uint32_t o0 = row + (uint32_t)((q * 32) ^ swm);
    uint32_t o1 = row + (uint32_t)((q * 32 + 16) ^ swm);
    cp16(o0, ph, sz);
    cp16(o1, ph + 16, sz);
    cp16(o0 + 16384, pl, sz);
    cp16(o1 + 16384, pl + 16, sz);
}

// ---------------- c2 gather (product path, 512 threads) ----------------
__device__ __forceinline__ void gather2p(const float* __restrict__ node,
                                         const int* __restrict__ vi,
                                         const int* __restrict__ vj,
                                         int tbase, int tid, float4* v) {
    int r = tid >> 2, q = tid & 3;
    int e = tbase + r;
    if (e < NEDGE) {
        const float4* a = (const float4*)(node + (size_t)vi[e] * 64) + q * 4;
        const float4* b = (const float4*)(node + (size_t)vj[e] * 64) + q * 4;
#pragma unroll
        for (int i = 0; i < 4; i++) {
            float4 x = a[i], y = b[i];
            v[i] = make_float4(x.x * y.x, x.y * y.y, x.z * y.z, x.w * y.w);
        }
    } else {
#pragma unroll
        for (int i = 0; i < 4; i++) v[i] = make_float4(0.f, 0.f, 0.f, 0.f);
    }
}
__device__ __forceinline__ void cvt_store4(const float4* v, char* buf, int tid) {
    int r = tid >> 2, q = tid & 3;
    int swm = (r & 7) << 4;
#pragma unroll
    for (int i = 0; i < 4; i++) {
        uint32_t h0, l0, h1, l1;
        cvt_pair(v[i].x, v[i].y, h0, l0);
        cvt_pair(v[i].z, v[i].w, h1, l1);
        int off = r * 128 + ((q * 32 + i * 8) ^ swm);
        *(uint2*)(buf + off) = make_uint2(h0, h1);
        *(uint2*)(buf + 16384 + off) = make_uint2(l0, l1);
    }
}

// ============================================================================
// K2: c3 linear — 3-buffer cp.async pipeline, 1 sync/panel, W-lo via LDG frags
// ============================================================================
struct C3Src { const unsigned short* h; const unsigned short* l; };

__global__ void __launch_bounds__(512, 1) k_c3mm(const int* __restrict__ ii,
                                                 const int* __restrict__ ij,
                                                 const int* __restrict__ ik,
                                                 const int* __restrict__ iji,
                                                 const int* __restrict__ ikj) {
    extern __shared__ __align__(128) char smal[];
    __shared__ float sred[256];
    const uint32_t sbal = smem_u32(smal);
    const int tid = threadIdx.x, wid = tid >> 5, lane = tid & 31;
    const int wm = wid >> 2, wn = wid & 3;
    {
        const uint4* srch = (const uint4*)g_wbh;
        uint4* dsth = (uint4*)smal;
        for (int i = tid; i < 5120; i += 512) dsth[i] = srch[i];
    }
    if (tid < 256) sred[tid] = 0.0f;
    __syncthreads();

    const int* idxs[5] = {ii, ij, ik, iji, ikj};

    // prefetch panels gp=0,1
#define PREFETCH(G) do {                                                        \
        int _g = (G);                                                           \
        int _m = _g / 5, _p = _g - 5 * _m;                                      \
        int _tb = (blockIdx.x + _m * gridDim.x) * TILE_M;                       \
        const unsigned short* _sh = (_p < 3) ? g_nodeh : g_edgeh;               \
        const unsigned short* _sl = (_p < 3) ? g_nodel : g_edgel;               \
        issue_panel(_sh, _sl, idxs[_p], _tb,                                    \
                    sbal + SW_C3A + (uint32_t)(_g % 3) * 32768u, tid);          \
        CP_COMMIT();                                                            \
    } while (0)

    PREFETCH(0);
    PREFETCH(1);

    const int lr = lane >> 2, lq = lane & 3;
    int gp = 0;
    for (int tile = blockIdx.x; tile < NT_TILES; tile += gridDim.x) {
        const int tbase = tile * TILE_M;
        float acc[2][4][4];
#pragma unroll
        for (int mt = 0; mt < 2; mt++)
#pragma unroll
            for (int nt = 0; nt < 4; nt++)
#pragma unroll
                for (int u = 0; u < 4; u++) acc[mt][nt][u] = 0.0f;

#pragma unroll
        for (int p = 0; p < 5; p++, gp++) {
            CP_WAIT1();
            __syncthreads();
            PREFETCH(gp + 2);
            mma_panelL(sbal + SW_C3A + (uint32_t)(gp % 3) * 32768u,
                       sbal + (uint32_t)p * 16384u, p, wn, wm, lane, acc);
        }

        // epilogue: y3 stores + fused column stats
#pragma unroll
        for (int mt = 0; mt < 2; mt++) {
            int gr = tbase + wm * 32 + mt * 16 + lr;
#pragma unroll
            for (int nt = 0; nt < 4; nt++) {
                int col = wn * 32 + nt * 8 + lq * 2;
                if (gr < NTRI)
                    *(float2*)&g_y3[(size_t)gr * CC + col] = make_float2(acc[mt][nt][0], acc[mt][nt][1]);
                if (gr + 8 < NTRI)
                    *(float2*)&g_y3[(size_t)(gr + 8) * CC + col] = make_float2(acc[mt][nt][2], acc[mt][nt][3]);
            }
        }
        float sv[8], qv[8];
#pragma unroll
        for (int nt = 0; nt < 4; nt++)
#pragma unroll
            for (int j = 0; j < 2; j++) {
                float a0 = acc[0][nt][j], a1 = acc[0][nt][j + 2];
                float a2 = acc[1][nt][j], a3 = acc[1][nt][j + 2];
                sv[nt * 2 + j] = a0 + a1 + a2 + a3;
                qv[nt * 2 + j] = a0 * a0 + a1 * a1 + a2 * a2 + a3 * a3;
            }
#pragma unroll
        for (int i = 0; i < 8; i++) {
#pragma unroll
            for (int m = 4; m < 32; m <<= 1) {
                sv[i] += __shfl_xor_sync(0xffffffff, sv[i], m);
                qv[i] += __shfl_xor_sync(0xffffffff, qv[i], m);
            }
        }
        if (lane < 4) {
#pragma unroll
            for (int i = 0; i < 8; i++) {
                int col = wn * 32 + (i >> 1) * 8 + lane * 2 + (i & 1);
                atomicAdd(&sred[col], sv[i]);
                atomicAdd(&sred[128 + col], qv[i]);
            }
        }
    }
    __syncthreads();
    if (tid < 256) atomicAdd(&g_sumbuf[256 + tid], sred[tid]);
#undef PREFETCH
}

// ============================================================================
// K1: c2 linear — 512 threads, 16 warps of 32x32, cross-tile double buffer
// ============================================================================
__global__ void __launch_bounds__(512, 1) k_c2mm(const float* __restrict__ node,
                                                 const int* __restrict__ vi,
                                                 const int* __restrict__ vj) {
    extern __shared__ __align__(128) char smal[];
    __shared__ float sred[256];
    const uint32_t sbal = smem_u32(smal);
    const int tid = threadIdx.x, wid = tid >> 5, lane = tid & 31;
    const int wm = wid >> 2, wn = wid & 3;
    {
        const uint4* srch = (const uint4*)g_w2h;
        const uint4* srcl = (const uint4*)g_w2l;
        uint4* dsth = (uint4*)smal;
        uint4* dstl = (uint4*)(smal + 16384);
        for (int i = tid; i < 1024; i += 512) { dsth[i] = srch[i]; dstl[i] = srcl[i]; }
    }
    if (tid < 256) sred[tid] = 0.0f;

    float4 v[4];
    int tile = blockIdx.x;
    if (tile < NE_TILES) {
        gather2p(node, vi, vj, tile * TILE_M, tid, v);
        cvt_store4(v, smal + SW2_A, tid);
    }
    __syncthreads();
    uint32_t parOff = 0;
    const int lr = lane >> 2, lq = lane & 3;

    for (; tile < NE_TILES; tile += gridDim.x) {
        const int tbase = tile * TILE_M;
        float acc[2][4][4];
#pragma unroll
        for (int mt = 0; mt < 2; mt++)
#pragma unroll
            for (int nt = 0; nt < 4; nt++)
#pragma unroll
                for (int u = 0; u < 4; u++) acc[mt][nt][u] = 0.0f;

        int ntile = tile + gridDim.x;
        if (ntile < NE_TILES) gather2p(node, vi, vj, ntile * TILE_M, tid, v);
        mma_panel16(sbal + SW2_A + parOff, sbal, sbal + 16384u, wm, wn, lane, acc);
        if (ntile < NE_TILES) cvt_store4(v, smal + SW2_A + (parOff ^ 32768u), tid);

#pragma unroll
        for (int mt = 0; mt < 2; mt++) {
            int gr = tbase + wm * 32 + mt * 16 + lr;
#pragma unroll
            for (int nt = 0; nt < 4; nt++) {
                int col = wn * 32 + nt * 8 + lq * 2;
                if (gr < NEDGE)
                    *(float2*)&g_y2[(size_t)gr * CC + col] = make_float2(acc[mt][nt][0], acc[mt][nt][1]);
                if (gr + 8 < NEDGE)
                    *(float2*)&g_y2[(size_t)(gr + 8) * CC + col] = make_float2(acc[mt][nt][2], acc[mt][nt][3]);
            }
        }
        float sv[8], qv[8];
#pragma unroll
        for (int nt = 0; nt < 4; nt++)
#pragma unroll
            for (int j = 0; j < 2; j++) {
                float a0 = acc[0][nt][j], a1 = acc[0][nt][j + 2];
                float a2 = acc[1][nt][j], a3 = acc[1][nt][j + 2];
                sv[nt * 2 + j] = a0 + a1 + a2 + a3;
                qv[nt * 2 + j] = a0 * a0 + a1 * a1 + a2 * a2 + a3 * a3;
            }
#pragma unroll
        for (int i = 0; i < 8; i++) {
#pragma unroll
            for (int m = 4; m < 32; m <<= 1) {
                sv[i] += __shfl_xor_sync(0xffffffff, sv[i], m);
                qv[i] += __shfl_xor_sync(0xffffffff, qv[i], m);
            }
        }
        if (lane < 4) {
#pragma unroll
            for (int i = 0; i < 8; i++) {
                int col = wn * 32 + (i >> 1) * 8 + lane * 2 + (i & 1);
                atomicAdd(&sred[col], sv[i]);
                atomicAdd(&sred[128 + col], qv[i]);
            }
        }
        __syncthreads();
        parOff ^= 32768u;
    }
    __syncthreads();
    if (tid < 256) atomicAdd(&g_sumbuf[tid], sred[tid]);
}

// ============================================================================
__global__ void k_stats1(const float* __restrict__ gc2, const float* __restrict__ bc2,
                         const float* __restrict__ gc3, const float* __restrict__ bc3) {
    int tid = threadIdx.x;  // 256
    if (tid < 128) {
        float mean = g_sumbuf[tid] * (1.0f / NEDGE);
        float var  = g_sumbuf[128 + tid] * (1.0f / NEDGE) - mean * mean;
        float a = gc2[tid] * rsqrtf(var + EPSF);
        g_ab[tid] = a;
        g_ab[128 + tid] = bc2[tid] - mean * a;
    } else {
        int c = tid - 128;
        float mean = g_sumbuf[256 + c] * (1.0f / NTRI);
        float var  = g_sumbuf[384 + c] * (1.0f / NTRI) - mean * mean;
        float a = gc3[c] * rsqrtf(var + EPSF);
        g_ab[256 + c] = a;
        g_ab[384 + c] = bc3[c] - mean * a;
    }
}

// ============================================================================
__global__ void __launch_bounds__(256) k_c2act() {
    __shared__ float sred[128];
    int tid = threadIdx.x;
    if (tid < 128) sred[tid] = 0.0f;
    __syncthreads();
    size_t i0 = (size_t)blockIdx.x * 256 + tid;
    int c = (int)(i0 & 15) * 4;
    float4 af = *(const float4*)&g_ab[c];
    float4 bf = *(const float4*)&g_ab[128 + c];
    float4 ac = *(const float4*)&g_ab[64 + c];
    float4 bc = *(const float4*)&g_ab[192 + c];
    float s[4] = {0, 0, 0, 0}, q[4] = {0, 0, 0, 0};
    size_t stride = (size_t)gridDim.x * 256;
    size_t n = (size_t)NEDGE * 16;
    for (size_t idx = i0; idx < n; idx += stride) {
        size_t e = idx >> 4;
        float4 yf = *(const float4*)&g_y2[(e << 7) + c];
        float4 yc = *(const float4*)&g_y2[(e << 7) + 64 + c];
        float4 g;
        g.x = sigmoidf_(yf.x * af.x + bf.x) * tanhf(yc.x * ac.x + bc.x);
        g.y = sigmoidf_(yf.y * af.y + bf.y) * tanhf(yc.y * ac.y + bc.y);
        g.z = sigmoidf_(yf.z * af.z + bf.z) * tanhf(yc.z * ac.z + bc.z);
        g.w = sigmoidf_(yf.w * af.w + bf.w) * tanhf(yc.w * ac.w + bc.w);
        *(float4*)&g_g2[idx << 2] = g;
        s[0] += g.x; s[1] += g.y; s[2] += g.z; s[3] += g.w;
        q[0] += g.x * g.x; q[1] += g.y * g.y; q[2] += g.z * g.z; q[3] += g.w * g.w;
    }
#pragma unroll
    for (int u = 0; u < 4; u++) {
        atomicAdd(&sred[c + u], s[u]);
        atomicAdd(&sred[64 + c + u], q[u]);
    }
    __syncthreads();
    if (tid < 128) atomicAdd(&g_sumbuf[512 + tid], sred[tid]);
}

// ============================================================================
__global__ void __launch_bounds__(256) k_c3act(const int* __restrict__ iji) {
    size_t i0 = (size_t)blockIdx.x * 256 + threadIdx.x;
    int c = (int)(i0 & 15) * 4;
    float4 af = *(const float4*)&g_ab[256 + c];
    float4 bf = *(const float4*)&g_ab[384 + c];
    float4 ac = *(const float4*)&g_ab[320 + c];
    float4 bc = *(const float4*)&g_ab[448 + c];
    size_t stride = (size_t)gridDim.x * 256;
    size_t n = (size_t)NTRI * 16;
    for (size_t idx = i0; idx < n; idx += stride) {
        size_t t = idx >> 4;
        float4 yf = *(const float4*)&g_y3[(t << 7) + c];
        float4 yc = *(const float4*)&g_y3[(t << 7) + 64 + c];
        float m0 = sigmoidf_(yf.x * af.x + bf.x) * tanhf(yc.x * ac.x + bc.x);
        float m1 = sigmoidf_(yf.y * af.y + bf.y) * tanhf(yc.y * ac.y + bc.y);
        float m2 = sigmoidf_(yf.z * af.z + bf.z) * tanhf(yc.z * ac.z + bc.z);
        float m3 = sigmoidf_(yf.w * af.w + bf.w) * tanhf(yc.w * ac.w + bc.w);
        float* dst = g_agg + ((size_t)iji[t] << 6) + c;
        asm volatile("red.global.v4.f32.add [%0], {%1, %2, %3, %4};"
                     :: "l"(dst), "f"(m0), "f"(m1), "f"(m2), "f"(m3) : "memory");
    }
}

// ============================================================================
__global__ void __launch_bounds__(256) k_aggstats() {
    __shared__ float sred[128];
    int tid = threadIdx.x;
    if (tid < 128) sred[tid] = 0.0f;
    __syncthreads();
    size_t i0 = (size_t)blockIdx.x * 256 + tid;
    int c = (int)(i0 & 15) * 4;
    float s[4] = {0, 0, 0, 0}, q[4] = {0, 0, 0, 0};
    size_t stride = (size_t)gridDim.x * 256;
    size_t n = (size_t)NEDGE * 16;
    for (size_t idx = i0; idx < n; idx += stride) {
        float4 vv = *(const float4*)&g_agg[idx << 2];
        s[0] += vv.x; s[1] += vv.y; s[2] += vv.z; s[3] += vv.w;
        q[0] += vv.x * vv.x; q[1] += vv.y * vv.y; q[2] += vv.z * vv.z; q[3] += vv.w * vv.w;
    }
#pragma unroll
    for (int u = 0; u < 4; u++) {
        atomicAdd(&sred[c + u], s[u]);
        atomicAdd(&sred[64 + c + u], q[u]);
    }
    __syncthreads();
    if (tid < 128) atomicAdd(&g_sumbuf[640 + tid], sred[tid]);
}

// ============================================================================
__global__ void k_stats2(const float* __restrict__ g22, const float* __restrict__ b22,
                         const float* __restrict__ g32, const float* __restrict__ b32) {
    int tid = threadIdx.x;  // 128
    if (tid < 64) {
        float mean = g_sumbuf[512 + tid] * (1.0f / NEDGE);
        float var  = g_sumbuf[576 + tid] * (1.0f / NEDGE) - mean * mean;
        float a = g22[tid] * rsqrtf(var + EPSF);
        g_ab[512 + tid] = a;
        g_ab[576 + tid] = b22[tid] - mean * a;
    } else {
        int c = tid - 64;
        float mean = g_sumbuf[640 + c] * (1.0f / NEDGE);
        float var  = g_sumbuf[704 + c] * (1.0f / NEDGE) - mean * mean;
        float a = g32[c] * rsqrtf(var + EPSF);
        g_ab[640 + c] = a;
        g_ab[704 + c] = b32[c] - mean * a;
    }
}

// ============================================================================
__global__ void __launch_bounds__(256) k_out(const float* __restrict__ edge,
                                             float* __restrict__ out) {
    size_t i0 = (size_t)blockIdx.x * 256 + threadIdx.x;
    int c = (int)(i0 & 15) * 4;
    float4 a2 = *(const float4*)&g_ab[512 + c];
    float4 b2v = *(const float4*)&g_ab[576 + c];
    float4 a3 = *(const float4*)&g_ab[640 + c];
    float4 b3v = *(const float4*)&g_ab[704 + c];
    size_t stride = (size_t)gridDim.x * 256;
    size_t n = (size_t)NEDGE * 16;
    for (size_t idx = i0; idx < n; idx += stride) {
        float4 e = *(const float4*)&edge[idx << 2];
        float4 g = *(const float4*)&g_g2[idx << 2];
        float4 a = *(const float4*)&g_agg[idx << 2];
        float4 o;
        o.x = tanhf(e.x + g.x * a2.x + b2v.x + a.x * a3.x + b3v.x);
        o.y = tanhf(e.y + g.y * a2.y + b2v.y + a.y * a3.y + b3v.y);
        o.z = tanhf(e.z + g.z * a2.z + b2v.z + a.z * a3.z + b3v.z);
        o.w = tanhf(e.w + g.w * a2.w + b2v.w + a.w * a3.w + b3v.w);
        *(float4*)&out[idx << 2] = o;
    }
}

// ============================================================================
extern "C" void kernel_launch(void* const* d_in, const int* in_sizes, int n_in,
                              void* d_out, int out_size) {
    const float* node = (const float*)d_in[0];
    const float* edge = (const float*)d_in[1];
    const int* vi     = (const int*)d_in[2];
    const int* vj     = (const int*)d_in[3];
    const int* idx_i  = (const int*)d_in[4];
    const int* idx_j  = (const int*)d_in[5];
    const int* idx_k  = (const int*)d_in[6];
    const int* idx_ji = (const int*)d_in[7];
    const int* idx_kj = (const int*)d_in[8];
    const float* W2   = (const float*)d_in[9];
    const float* W3   = (const float*)d_in[11];
    const float* gc2  = (const float*)d_in[13];
    const float* bc2  = (const float*)d_in[14];
    const float* gc3  = (const float*)d_in[15];
    const float* bc3  = (const float*)d_in[16];
    const float* g22  = (const float*)d_in[17];
    const float* b22  = (const float*)d_in[18];
    const float* g32  = (const float*)d_in[19];
    const float* b32  = (const float*)d_in[20];
    float* out = (float*)d_out;

    cudaFuncSetAttribute(k_c2mm, cudaFuncAttributeMaxDynamicSharedMemorySize, SMEM_C2);
    cudaFuncSetAttribute(k_c3mm, cudaFuncAttributeMaxDynamicSharedMemorySize, SMEM_C3);

    k_zero<<<1024, 256>>>();
    k_prepw<<<160, 256>>>(W3);
    k_prepx<<<2048, 256>>>(node, edge);
    k_c3mm<<<148, 512, SMEM_C3>>>(idx_i, idx_j, idx_k, idx_ji, idx_kj);
    k_prepw2<<<32, 256>>>(W2);
    k_c2mm<<<148, 512, SMEM_C2>>>(node, vi, vj);
    k_stats1<<<1, 256>>>(gc2, bc2, gc3, bc3);
    k_c2act<<<512, 256>>>();
    k_c3act<<<2048, 256>>>(idx_ji);
    k_aggstats<<<512, 256>>>();
    k_stats2<<<1, 128>>>(g22, b22, g32, b32);
    k_out<<<512, 256>>>(edge, out);
}

// round 11
// speedup vs baseline: 1.1324x; 1.0291x over previous
#include <cuda_runtime.h>
#include <cuda_bf16.h>
#include <cstdint>
#include <math.h>

#define HN 64
#define HE 64
#define NNODE 50000
#define NEDGE 200000
#define NTRI  600000
#define CC 128
#define D3 320
#define EPSF 1e-5f
#define TILE_M 128
#define NT_TILES ((NTRI + TILE_M - 1) / TILE_M)   // 4688
#define NE_TILES ((NEDGE + TILE_M - 1) / TILE_M)  // 1563

// ---------------- scratch ----------------
__device__ float g_y2[(size_t)NEDGE * CC];
__device__ float g_y3[(size_t)NTRI * CC];
__device__ float g_g2[(size_t)NEDGE * HE];
__device__ float g_agg[(size_t)NEDGE * HE];
__device__ unsigned short g_wbh[128 * 320];     // W3 hi bf16, panelized+swizzled
__device__ unsigned short g_wbl[128 * 320];     // W3 lo bf16, same layout
__device__ unsigned short g_w2h[128 * 64];      // W2 hi bf16
__device__ unsigned short g_w2l[128 * 64];      // W2 lo bf16
__device__ unsigned short g_nodeh[(size_t)NNODE * 64];
__device__ unsigned short g_nodel[(size_t)NNODE * 64];
__device__ unsigned short g_edgeh[(size_t)NEDGE * 64];
__device__ unsigned short g_edgel[(size_t)NEDGE * 64];
__device__ float g_sumbuf[768];
__device__ float g_ab[768];

// ---------------- helpers ----------------
__device__ __forceinline__ float sigmoidf_(float x) { return 1.0f / (1.0f + __expf(-x)); }
__device__ __forceinline__ uint32_t smem_u32(const void* p) {
    uint32_t a;
    asm("{ .reg .u64 t; cvta.to.shared.u64 t, %1; cvt.u32.u64 %0, t; }" : "=r"(a) : "l"(p));
    return a;
}
__device__ __forceinline__ uint32_t bfpack(float f0, float f1) {   // f0 -> low half
    uint32_t r;
    asm("cvt.rn.bf16x2.f32 %0, %1, %2;" : "=r"(r) : "f"(f1), "f"(f0));
    return r;
}
__device__ __forceinline__ void cvt_pair(float f0, float f1, uint32_t& h, uint32_t& l) {
    h = bfpack(f0, f1);
    float r0 = f0 - __uint_as_float((h & 0xFFFFu) << 16);
    float r1 = f1 - __uint_as_float(h & 0xFFFF0000u);
    l = bfpack(r0, r1);
}
__device__ __forceinline__ void ldsm_x4(uint32_t addr, uint32_t* r) {
    asm volatile("ldmatrix.sync.aligned.m8n8.x4.shared.b16 {%0,%1,%2,%3}, [%4];"
        : "=r"(r[0]), "=r"(r[1]), "=r"(r[2]), "=r"(r[3]) : "r"(addr));
}
__device__ __forceinline__ void mma_bf16(float* c, const uint32_t* a, const uint32_t* b) {
    asm volatile("mma.sync.aligned.m16n8k16.row.col.f32.bf16.bf16.f32 "
        "{%0,%1,%2,%3}, {%4,%5,%6,%7}, {%8,%9}, {%0,%1,%2,%3};"
        : "+f"(c[0]), "+f"(c[1]), "+f"(c[2]), "+f"(c[3])
        : "r"(a[0]), "r"(a[1]), "r"(a[2]), "r"(a[3]), "r"(b[0]), "r"(b[1]));
}
__device__ __forceinline__ uint32_t a_addr(uint32_t base, int r0, int k0, int lane) {
    int row = r0 + (lane & 15);
    int kk = k0 + ((lane >> 4) << 3);
    return base + row * 128 + ((kk * 2) ^ ((row & 7) << 4));
}
__device__ __forceinline__ uint32_t b_addr(uint32_t base, int n0, int k0, int lane) {
    int row = n0 + (lane & 7) + ((lane >> 4) << 3);
    int kk = k0 + (((lane >> 3) & 1) << 3);
    return base + row * 128 + ((kk * 2) ^ ((row & 7) << 4));
}
__device__ __forceinline__ void cp16(uint32_t dst, const void* src, int sz) {
    asm volatile("cp.async.cg.shared.global [%0], [%1], 16, %2;"
                 :: "r"(dst), "l"(src), "r"(sz) : "memory");
}
#define CP_COMMIT() asm volatile("cp.async.commit_group;" ::: "memory")
#define CP_WAIT1()  asm volatile("cp.async.wait_group 1;" ::: "memory")

// c3 SMEM: W-hi [0,81920), W-lo ring 3x16K [81920,131072), A ring 3x32K [131072, 229376)
#define SW_WL 81920
#define SW_A  131072
#define SMEM_C3 229376
// c2 SMEM: W2h [0,16K), W2l [16K,32K), A bufs x2 [32K, 96K)
#define SW2_A 32768
#define SMEM_C2 (SW2_A + 65536)        // 98304 B

// ============================================================================
// K0: combined prep — zero agg/sums, split W3 and W2 into bf16 hi/lo images
// ============================================================================
__global__ void __launch_bounds__(256) k_prep(const float* __restrict__ W3,
                                              const float* __restrict__ W2) {
    size_t i = (size_t)blockIdx.x * 256 + threadIdx.x;
    size_t stride = (size_t)gridDim.x * 256;
    // zero g_agg (float4 view) + sumbuf
    size_t nagg = (size_t)NEDGE * HE / 4;
    float4 z = make_float4(0.f, 0.f, 0.f, 0.f);
    float4* p4 = (float4*)g_agg;
    for (size_t p = i; p < nagg; p += stride) p4[p] = z;
    if (i < 768) g_sumbuf[i] = 0.0f;
    // W3 split (40960 elems)
    for (size_t idx = i; idx < 128 * 320; idx += stride) {
        int n = (int)(idx / 320), k = (int)(idx - (size_t)n * 320);
        float w = W3[idx];
        __nv_bfloat16 hb = __float2bfloat16_rn(w);
        __nv_bfloat16 lb = __float2bfloat16_rn(w - __bfloat162float(hb));
        int p = k >> 6, kk = k & 63;
        uint32_t byte = (uint32_t)p * 16384u + (uint32_t)n * 128u + (uint32_t)((kk * 2) ^ ((n & 7) << 4));
        g_wbh[byte >> 1] = __bfloat16_as_ushort(hb);
        g_wbl[byte >> 1] = __bfloat16_as_ushort(lb);
    }
    // W2 split (8192 elems)
    for (size_t idx = i; idx < 128 * 64; idx += stride) {
        int n = (int)(idx >> 6), k = (int)(idx & 63);
        float w = W2[idx];
        __nv_bfloat16 hb = __float2bfloat16_rn(w);
        __nv_bfloat16 lb = __float2bfloat16_rn(w - __bfloat162float(hb));
        uint32_t byte = (uint32_t)n * 128u + (uint32_t)((k * 2) ^ ((n & 7) << 4));
        g_w2h[byte >> 1] = __bfloat16_as_ushort(hb);
        g_w2l[byte >> 1] = __bfloat16_as_ushort(lb);
    }
}
// node/edge bf16 hi/lo row images
__global__ void __launch_bounds__(256) k_prepx(const float* __restrict__ node,
                                               const float* __restrict__ edge) {
    size_t i = (size_t)blockIdx.x * 256 + threadIdx.x;
    size_t stride = (size_t)gridDim.x * 256;
    const size_t nn = (size_t)NNODE * 16;
    const size_t ne = (size_t)NEDGE * 16;
    for (size_t p = i; p < nn + ne; p += stride) {
        float4 v = (p < nn) ? ((const float4*)node)[p] : ((const float4*)edge)[p - nn];
        uint32_t h0, l0, h1, l1;
        cvt_pair(v.x, v.y, h0, l0);
        cvt_pair(v.z, v.w, h1, l1);
        if (p < nn) {
            ((uint2*)g_nodeh)[p] = make_uint2(h0, h1);
            ((uint2*)g_nodel)[p] = make_uint2(l0, l1);
        } else {
            ((uint2*)g_edgeh)[p - nn] = make_uint2(h0, h1);
            ((uint2*)g_edgel)[p - nn] = make_uint2(l0, l1);
        }
    }
}

// ---------------- MMA panel body (8-ldsm, all-smem operands) ----------------
__device__ __forceinline__ void mma_panel8(uint32_t abase, uint32_t wbh, uint32_t wbl,
                                           int wm, int wn, int lane, float acc[2][4][4]) {
    uint32_t abl = abase + 16384;
#pragma unroll
    for (int ks = 0; ks < 4; ks++) {
        int k0 = ks * 16;
        uint32_t ah[2][4], al[2][4], bh[2][4], bl[2][4];
        ldsm_x4(a_addr(abase, wm * 32, k0, lane), ah[0]);
        ldsm_x4(a_addr(abase, wm * 32 + 16, k0, lane), ah[1]);
        ldsm_x4(a_addr(abl, wm * 32, k0, lane), al[0]);
        ldsm_x4(a_addr(abl, wm * 32 + 16, k0, lane), al[1]);
        ldsm_x4(b_addr(wbh, wn * 32, k0, lane), bh[0]);
        ldsm_x4(b_addr(wbh, wn * 32 + 16, k0, lane), bh[1]);
        ldsm_x4(b_addr(wbl, wn * 32, k0, lane), bl[0]);
        ldsm_x4(b_addr(wbl, wn * 32 + 16, k0, lane), bl[1]);
#pragma unroll
        for (int mt = 0; mt < 2; mt++)
#pragma unroll
            for (int g = 0; g < 2; g++) {
                mma_bf16(acc[mt][2 * g],     ah[mt], &bh[g][0]);
                mma_bf16(acc[mt][2 * g + 1], ah[mt], &bh[g][2]);
                mma_bf16(acc[mt][2 * g],     ah[mt], &bl[g][0]);
                mma_bf16(acc[mt][2 * g + 1], ah[mt], &bl[g][2]);
                mma_bf16(acc[mt][2 * g],     al[mt], &bh[g][0]);
                mma_bf16(acc[mt][2 * g + 1], al[mt], &bh[g][2]);
            }
    }
}

// ---------------- c3 async feeds ----------------
__device__ __forceinline__ void issue_panel(const unsigned short* __restrict__ sh,
                                            const unsigned short* __restrict__ sl,
                                            const int* __restrict__ idx,
                                            int tbase, uint32_t abase, int tid) {
    int r = tid >> 2, q = tid & 3;
    int t = tbase + r;
    bool valid = (t < NTRI);
    int gi = valid ? idx[t] : 0;
    int sz = valid ? 16 : 0;
    const char* ph = (const char*)(sh + (size_t)gi * 64) + q * 32;
    const char* pl = (const char*)(sl + (size_t)gi * 64) + q * 32;
    int swm = (r & 7) << 4;
    uint32_t row = abase + (uint32_t)r * 128u;
    uint32_t o0 = row + (uint32_t)((q * 32) ^ swm);
    uint32_t o1 = row + (uint32_t)((q * 32 + 16) ^ swm);
    cp16(o0, ph, sz);
    cp16(o1, ph + 16, sz);
    cp16(o0 + 16384, pl, sz);
    cp16(o1 + 16384, pl + 16, sz);
}
__device__ __forceinline__ void issue_wlo(int p, uint32_t dst, int tid) {
    const char* src = (const char*)g_wbl + p * 16384 + tid * 32;
    cp16(dst + (uint32_t)tid * 32u, src, 16);
    cp16(dst + (uint32_t)tid * 32u + 16u, src + 16, 16);
}

// ---------------- c2 gather (product path, 512 threads) ----------------
__device__ __forceinline__ void gather2p(const float* __restrict__ node,
                                         const int* __restrict__ vi,
                                         const int* __restrict__ vj,
                                         int tbase, int tid, float4* v) {
    int r = tid >> 2, q = tid & 3;
    int e = tbase + r;
    if (e < NEDGE) {
        const float4* a = (const float4*)(node + (size_t)vi[e] * 64) + q * 4;
        const float4* b = (const float4*)(node + (size_t)vj[e] * 64) + q * 4;
#pragma unroll
        for (int i = 0; i < 4; i++) {
            float4 x = a[i], y = b[i];
            v[i] = make_float4(x.x * y.x, x.y * y.y, x.z * y.z, x.w * y.w);
        }
    } else {
#pragma unroll
        for (int i = 0; i < 4; i++) v[i] = make_float4(0.f, 0.f, 0.f, 0.f);
    }
}
__device__ __forceinline__ void cvt_store4(const float4* v, char* buf, int tid) {
    int r = tid >> 2, q = tid & 3;
    int swm = (r & 7) << 4;
#pragma unroll
    for (int i = 0; i < 4; i++) {
        uint32_t h0, l0, h1, l1;
        cvt_pair(v[i].x, v[i].y, h0, l0);
        cvt_pair(v[i].z, v[i].w, h1, l1);
        int off = r * 128 + ((q * 32 + i * 8) ^ swm);
        *(uint2*)(buf + off) = make_uint2(h0, h1);
        *(uint2*)(buf + 16384 + off) = make_uint2(l0, l1);
    }
}

// ============================================================================
// K2: c3 linear — 3-buffer cp.async pipeline (A + W-lo rings), 1 sync/panel
// ============================================================================
__global__ void __launch_bounds__(512, 1) k_c3mm(const int* __restrict__ ii,
                                                 const int* __restrict__ ij,
                                                 const int* __restrict__ ik,
                                                 const int* __restrict__ iji,
                                                 const int* __restrict__ ikj) {
    extern __shared__ __align__(128) char smal[];
    __shared__ float sred[256];
    const uint32_t sbal = smem_u32(smal);
    const int tid = threadIdx.x, wid = tid >> 5, lane = tid & 31;
    const int wm = wid >> 2, wn = wid & 3;
    {
        const uint4* srch = (const uint4*)g_wbh;
        uint4* dsth = (uint4*)smal;
        for (int i = tid; i < 5120; i += 512) dsth[i] = srch[i];
    }
    if (tid < 256) sred[tid] = 0.0f;
    __syncthreads();

    const int* idxs[5] = {ii, ij, ik, iji, ikj};

#define PREFETCH(G) do {                                                        \
        int _g = (G);                                                           \
        int _m = _g / 5, _p = _g - 5 * _m;                                      \
        int _tb = (blockIdx.x + _m * gridDim.x) * TILE_M;                       \
        const unsigned short* _sh = (_p < 3) ? g_nodeh : g_edgeh;               \
        const unsigned short* _sl = (_p < 3) ? g_nodel : g_edgel;               \
        uint32_t _buf = (uint32_t)(_g % 3);                                     \
        issue_panel(_sh, _sl, idxs[_p], _tb, sbal + SW_A + _buf * 32768u, tid); \
        issue_wlo(_p, sbal + SW_WL + _buf * 16384u, tid);                       \
        CP_COMMIT();                                                            \
    } while (0)

    PREFETCH(0);
    PREFETCH(1);

    const int lr = lane >> 2, lq = lane & 3;
    int gp = 0;
    for (int tile = blockIdx.x; tile < NT_TILES; tile += gridDim.x) {
        const int tbase = tile * TILE_M;
        float acc[2][4][4];
#pragma unroll
        for (int mt = 0; mt < 2; mt++)
#pragma unroll
            for (int nt = 0; nt < 4; nt++)
#pragma unroll
                for (int u = 0; u < 4; u++) acc[mt][nt][u] = 0.0f;

#pragma unroll
        for (int p = 0; p < 5; p++, gp++) {
            CP_WAIT1();
            __syncthreads();
            PREFETCH(gp + 2);
            uint32_t buf = (uint32_t)(gp % 3);
            mma_panel8(sbal + SW_A + buf * 32768u,
                       sbal + (uint32_t)p * 16384u,
                       sbal + SW_WL + buf * 16384u, wm, wn, lane, acc);
        }

        // epilogue: y3 stores + fused column stats
#pragma unroll
        for (int mt = 0; mt < 2; mt++) {
            int gr = tbase + wm * 32 + mt * 16 + lr;
#pragma unroll
            for (int nt = 0; nt < 4; nt++) {
                int col = wn * 32 + nt * 8 + lq * 2;
                if (gr < NTRI)
                    *(float2*)&g_y3[(size_t)gr * CC + col] = make_float2(acc[mt][nt][0], acc[mt][nt][1]);
                if (gr + 8 < NTRI)
                    *(float2*)&g_y3[(size_t)(gr + 8) * CC + col] = make_float2(acc[mt][nt][2], acc[mt][nt][3]);
            }
        }
        float sv[8], qv[8];
#pragma unroll
        for (int nt = 0; nt < 4; nt++)
#pragma unroll
            for (int j = 0; j < 2; j++) {
                float a0 = acc[0][nt][j], a1 = acc[0][nt][j + 2];
                float a2 = acc[1][nt][j], a3 = acc[1][nt][j + 2];
                sv[nt * 2 + j] = a0 + a1 + a2 + a3;
                qv[nt * 2 + j] = a0 * a0 + a1 * a1 + a2 * a2 + a3 * a3;
            }
#pragma unroll
        for (int i = 0; i < 8; i++) {
#pragma unroll
            for (int m = 4; m < 32; m <<= 1) {
                sv[i] += __shfl_xor_sync(0xffffffff, sv[i], m);
                qv[i] += __shfl_xor_sync(0xffffffff, qv[i], m);
            }
        }
        if (lane < 4) {
#pragma unroll
            for (int i = 0; i < 8; i++) {
                int col = wn * 32 + (i >> 1) * 8 + lane * 2 + (i & 1);
                atomicAdd(&sred[col], sv[i]);
                atomicAdd(&sred[128 + col], qv[i]);
            }
        }
    }
    __syncthreads();
    if (tid < 256) atomicAdd(&g_sumbuf[256 + tid], sred[tid]);
#undef PREFETCH
}

// ============================================================================
// K1: c2 linear — 512 threads, 16 warps of 32x32, cross-tile double buffer
// ============================================================================
__global__ void __launch_bounds__(512, 1) k_c2mm(const float* __restrict__ node,
                                                 const int* __restrict__ vi,
                                                 const int* __restrict__ vj) {
    extern __shared__ __align__(128) char smal[];
    __shared__ float sred[256];
    const uint32_t sbal = smem_u32(smal);
    const int tid = threadIdx.x, wid = tid >> 5, lane = tid & 31;
    const int wm = wid >> 2, wn = wid & 3;
    {
        const uint4* srch = (const uint4*)g_w2h;
        const uint4* srcl = (const uint4*)g_w2l;
        uint4* dsth = (uint4*)smal;
        uint4* dstl = (uint4*)(smal + 16384);
        for (int i = tid; i < 1024; i += 512) { dsth[i] = srch[i]; dstl[i] = srcl[i]; }
    }
    if (tid < 256) sred[tid] = 0.0f;

    float4 v[4];
    int tile = blockIdx.x;
    if (tile < NE_TILES) {
        gather2p(node, vi, vj, tile * TILE_M, tid, v);
        cvt_store4(v, smal + SW2_A, tid);
    }
    __syncthreads();
    uint32_t parOff = 0;
    const int lr = lane >> 2, lq = lane & 3;

    for (; tile < NE_TILES; tile += gridDim.x) {
        const int tbase = tile * TILE_M;
        float acc[2][4][4];
#pragma unroll
        for (int mt = 0; mt < 2; mt++)
#pragma unroll
            for (int nt = 0; nt < 4; nt++)
#pragma unroll
                for (int u = 0; u < 4; u++) acc[mt][nt][u] = 0.0f;

        int ntile = tile + gridDim.x;
        if (ntile < NE_TILES) gather2p(node, vi, vj, ntile * TILE_M, tid, v);
        mma_panel8(sbal + SW2_A + parOff, sbal, sbal + 16384u, wm, wn, lane, acc);
        if (ntile < NE_TILES) cvt_store4(v, smal + SW2_A + (parOff ^ 32768u), tid);

#pragma unroll
        for (int mt = 0; mt < 2; mt++) {
            int gr = tbase + wm * 32 + mt * 16 + lr;
#pragma unroll
            for (int nt = 0; nt < 4; nt++) {
                int col = wn * 32 + nt * 8 + lq * 2;
                if (gr < NEDGE)
                    *(float2*)&g_y2[(size_t)gr * CC + col] = make_float2(acc[mt][nt][0], acc[mt][nt][1]);
                if (gr + 8 < NEDGE)
                    *(float2*)&g_y2[(size_t)(gr + 8) * CC + col] = make_float2(acc[mt][nt][2], acc[mt][nt][3]);
            }
        }
        float sv[8], qv[8];
#pragma unroll
        for (int nt = 0; nt < 4; nt++)
#pragma unroll
            for (int j = 0; j < 2; j++) {
                float a0 = acc[0][nt][j], a1 = acc[0][nt][j + 2];
                float a2 = acc[1][nt][j], a3 = acc[1][nt][j + 2];
                sv[nt * 2 + j] = a0 + a1 + a2 + a3;
                qv[nt * 2 + j] = a0 * a0 + a1 * a1 + a2 * a2 + a3 * a3;
            }
#pragma unroll
        for (int i = 0; i < 8; i++) {
#pragma unroll
            for (int m = 4; m < 32; m <<= 1) {
                sv[i] += __shfl_xor_sync(0xffffffff, sv[i], m);
                qv[i] += __shfl_xor_sync(0xffffffff, qv[i], m);
            }
        }
        if (lane < 4) {
#pragma unroll
            for (int i = 0; i < 8; i++) {
                int col = wn * 32 + (i >> 1) * 8 + lane * 2 + (i & 1);
                atomicAdd(&sred[col], sv[i]);
                atomicAdd(&sred[128 + col], qv[i]);
            }
        }
        __syncthreads();
        parOff ^= 32768u;
    }
    __syncthreads();
    if (tid < 256) atomicAdd(&g_sumbuf[tid], sred[tid]);
}

// ============================================================================
__global__ void k_stats1(const float* __restrict__ gc2, const float* __restrict__ bc2,
                         const float* __restrict__ gc3, const float* __restrict__ bc3) {
    int tid = threadIdx.x;  // 256
    if (tid < 128) {
        float mean = g_sumbuf[tid] * (1.0f / NEDGE);
        float var  = g_sumbuf[128 + tid] * (1.0f / NEDGE) - mean * mean;
        float a = gc2[tid] * rsqrtf(var + EPSF);
        g_ab[tid] = a;
        g_ab[128 + tid] = bc2[tid] - mean * a;
    } else {
        int c = tid - 128;
        float mean = g_sumbuf[256 + c] * (1.0f / NTRI);
        float var  = g_sumbuf[384 + c] * (1.0f / NTRI) - mean * mean;
        float a = gc3[c] * rsqrtf(var + EPSF);
        g_ab[256 + c] = a;
        g_ab[384 + c] = bc3[c] - mean * a;
    }
}

// ============================================================================
__global__ void __launch_bounds__(256) k_c2act() {
    __shared__ float sred[128];
    int tid = threadIdx.x;
    if (tid < 128) sred[tid] = 0.0f;
    __syncthreads();
    size_t i0 = (size_t)blockIdx.x * 256 + tid;
    int c = (int)(i0 & 15) * 4;
    float4 af = *(const float4*)&g_ab[c];
    float4 bf = *(const float4*)&g_ab[128 + c];
    float4 ac = *(const float4*)&g_ab[64 + c];
    float4 bc = *(const float4*)&g_ab[192 + c];
    float s[4] = {0, 0, 0, 0}, q[4] = {0, 0, 0, 0};
    size_t stride = (size_t)gridDim.x * 256;
    size_t n = (size_t)NEDGE * 16;
    for (size_t idx = i0; idx < n; idx += stride) {
        size_t e = idx >> 4;
        float4 yf = *(const float4*)&g_y2[(e << 7) + c];
        float4 yc = *(const float4*)&g_y2[(e << 7) + 64 + c];
        float4 g;
        g.x = sigmoidf_(yf.x * af.x + bf.x) * tanhf(yc.x * ac.x + bc.x);
        g.y = sigmoidf_(yf.y * af.y + bf.y) * tanhf(yc.y * ac.y + bc.y);
        g.z = sigmoidf_(yf.z * af.z + bf.z) * tanhf(yc.z * ac.z + bc.z);
        g.w = sigmoidf_(yf.w * af.w + bf.w) * tanhf(yc.w * ac.w + bc.w);
        *(float4*)&g_g2[idx << 2] = g;
        s[0] += g.x; s[1] += g.y; s[2] += g.z; s[3] += g.w;
        q[0] += g.x * g.x; q[1] += g.y * g.y; q[2] += g.z * g.z; q[3] += g.w * g.w;
    }
#pragma unroll
    for (int u = 0; u < 4; u++) {
        atomicAdd(&sred[c + u], s[u]);
        atomicAdd(&sred[64 + c + u], q[u]);
    }
    __syncthreads();
    if (tid < 128) atomicAdd(&g_sumbuf[512 + tid], sred[tid]);
}

// ============================================================================
__global__ void __launch_bounds__(256) k_c3act(const int* __restrict__ iji) {
    size_t i0 = (size_t)blockIdx.x * 256 + threadIdx.x;
    int c = (int)(i0 & 15) * 4;
    float4 af = *(const float4*)&g_ab[256 + c];
    float4 bf = *(const float4*)&g_ab[384 + c];
    float4 ac = *(const float4*)&g_ab[320 + c];
    float4 bc = *(const float4*)&g_ab[448 + c];
    size_t stride = (size_t)gridDim.x * 256;
    size_t n = (size_t)NTRI * 16;
    for (size_t idx = i0; idx < n; idx += stride) {
        size_t t = idx >> 4;
        float4 yf = *(const float4*)&g_y3[(t << 7) + c];
        float4 yc = *(const float4*)&g_y3[(t << 7) + 64 + c];
        float m0 = sigmoidf_(yf.x * af.x + bf.x) * tanhf(yc.x * ac.x + bc.x);
        float m1 = sigmoidf_(yf.y * af.y + bf.y) * tanhf(yc.y * ac.y + bc.y);
        float m2 = sigmoidf_(yf.z * af.z + bf.z) * tanhf(yc.z * ac.z + bc.z);
        float m3 = sigmoidf_(yf.w * af.w + bf.w) * tanhf(yc.w * ac.w + bc.w);
        float* dst = g_agg + ((size_t)iji[t] << 6) + c;
        asm volatile("red.global.v4.f32.add [%0], {%1, %2, %3, %4};"
                     :: "l"(dst), "f"(m0), "f"(m1), "f"(m2), "f"(m3) : "memory");
    }
}

// ============================================================================
__global__ void __launch_bounds__(256) k_aggstats() {
    __shared__ float sred[128];
    int tid = threadIdx.x;
    if (tid < 128) sred[tid] = 0.0f;
    __syncthreads();
    size_t i0 = (size_t)blockIdx.x * 256 + tid;
    int c = (int)(i0 & 15) * 4;
    float s[4] = {0, 0, 0, 0}, q[4] = {0, 0, 0, 0};
    size_t stride = (size_t)gridDim.x * 256;
    size_t n = (size_t)NEDGE * 16;
    for (size_t idx = i0; idx < n; idx += stride) {
        float4 vv = *(const float4*)&g_agg[idx << 2];
        s[0] += vv.x; s[1] += vv.y; s[2] += vv.z; s[3] += vv.w;
        q[0] += vv.x * vv.x; q[1] += vv.y * vv.y; q[2] += vv.z * vv.z; q[3] += vv.w * vv.w;
    }
#pragma unroll
    for (int u = 0; u < 4; u++) {
        atomicAdd(&sred[c + u], s[u]);
        atomicAdd(&sred[64 + c + u], q[u]);
    }
    __syncthreads();
    if (tid < 128) atomicAdd(&g_sumbuf[640 + tid], sred[tid]);
}

// ============================================================================
__global__ void k_stats2(const float* __restrict__ g22, const float* __restrict__ b22,
                         const float* __restrict__ g32, const float* __restrict__ b32) {
    int tid = threadIdx.x;  // 128
    if (tid < 64) {
        float mean = g_sumbuf[512 + tid] * (1.0f / NEDGE);
        float var  = g_sumbuf[576 + tid] * (1.0f / NEDGE) - mean * mean;
        float a = g22[tid] * rsqrtf(var + EPSF);
        g_ab[512 + tid] = a;
        g_ab[576 + tid] = b22[tid] - mean * a;
    } else {
        int c = tid - 64;
        float mean = g_sumbuf[640 + c] * (1.0f / NEDGE);
        float var  = g_sumbuf[704 + c] * (1.0f / NEDGE) - mean * mean;
        float a = g32[c] * rsqrtf(var + EPSF);
        g_ab[640 + c] = a;
        g_ab[704 + c] = b32[c] - mean * a;
    }
}

// ============================================================================
__global__ void __launch_bounds__(256) k_out(const float* __restrict__ edge,
                                             float* __restrict__ out) {
    size_t i0 = (size_t)blockIdx.x * 256 + threadIdx.x;
    int c = (int)(i0 & 15) * 4;
    float4 a2 = *(const float4*)&g_ab[512 + c];
    float4 b2v = *(const float4*)&g_ab[576 + c];
    float4 a3 = *(const float4*)&g_ab[640 + c];
    float4 b3v = *(const float4*)&g_ab[704 + c];
    size_t stride = (size_t)gridDim.x * 256;
    size_t n = (size_t)NEDGE * 16;
    for (size_t idx = i0; idx < n; idx += stride) {
        float4 e = *(const float4*)&edge[idx << 2];
        float4 g = *(const float4*)&g_g2[idx << 2];
        float4 a = *(const float4*)&g_agg[idx << 2];
        float4 o;
        o.x = tanhf(e.x + g.x * a2.x + b2v.x + a.x * a3.x + b3v.x);
        o.y = tanhf(e.y + g.y * a2.y + b2v.y + a.y * a3.y + b3v.y);
        o.z = tanhf(e.z + g.z * a2.z + b2v.z + a.z * a3.z + b3v.z);
        o.w = tanhf(e.w + g.w * a2.w + b2v.w + a.w * a3.w + b3v.w);
        *(float4*)&out[idx << 2] = o;
    }
}

// ============================================================================
extern "C" void kernel_launch(void* const* d_in, const int* in_sizes, int n_in,
                              void* d_out, int out_size) {
    const float* node = (const float*)d_in[0];
    const float* edge = (const float*)d_in[1];
    const int* vi     = (const int*)d_in[2];
    const int* vj     = (const int*)d_in[3];
    const int* idx_i  = (const int*)d_in[4];
    const int* idx_j  = (const int*)d_in[5];
    const int* idx_k  = (const int*)d_in[6];
    const int* idx_ji = (const int*)d_in[7];
    const int* idx_kj = (const int*)d_in[8];
    const float* W2   = (const float*)d_in[9];
    const float* W3   = (const float*)d_in[11];
    const float* gc2  = (const float*)d_in[13];
    const float* bc2  = (const float*)d_in[14];
    const float* gc3  = (const float*)d_in[15];
    const float* bc3  = (const float*)d_in[16];
    const float* g22  = (const float*)d_in[17];
    const float* b22  = (const float*)d_in[18];
    const float* g32  = (const float*)d_in[19];
    const float* b32  = (const float*)d_in[20];
    float* out = (float*)d_out;

    cudaFuncSetAttribute(k_c2mm, cudaFuncAttributeMaxDynamicSharedMemorySize, SMEM_C2);
    cudaFuncSetAttribute(k_c3mm, cudaFuncAttributeMaxDynamicSharedMemorySize, SMEM_C3);

    k_prep<<<1024, 256>>>(W3, W2);
    k_prepx<<<2048, 256>>>(node, edge);
    k_c3mm<<<148, 512, SMEM_C3>>>(idx_i, idx_j, idx_k, idx_ji, idx_kj);
    k_c2mm<<<148, 512, SMEM_C2>>>(node, vi, vj);
    k_stats1<<<1, 256>>>(gc2, bc2, gc3, bc3);
    k_c2act<<<512, 256>>>();
    k_c3act<<<2048, 256>>>(idx_ji);
    k_aggstats<<<512, 256>>>();
    k_stats2<<<1, 128>>>(g22, b22, g32, b32);
    k_out<<<512, 256>>>(edge, out);
}

// round 12
// speedup vs baseline: 1.2859x; 1.1356x over previous
#include <cuda_runtime.h>
#include <cuda_bf16.h>
#include <cuda_fp16.h>
#include <cstdint>
#include <math.h>

#define HN 64
#define HE 64
#define NNODE 50000
#define NEDGE 200000
#define NTRI  600000
#define CC 128
#define D3 320
#define EPSF 1e-5f
#define TILE_M 128
#define NT_TILES ((NTRI + TILE_M - 1) / TILE_M)   // 4688
#define NE_TILES ((NEDGE + TILE_M - 1) / TILE_M)  // 1563

// ---------------- scratch ----------------
__device__ float g_y2[(size_t)NEDGE * CC];
__device__ float g_y3[(size_t)NTRI * CC];
__device__ float g_g2[(size_t)NEDGE * HE];
__device__ float g_agg[(size_t)NEDGE * HE];
__device__ unsigned short g_wbh[128 * 320];     // W3 hi fp16, panelized+swizzled
__device__ unsigned short g_wbl[128 * 320];     // W3 lo fp16, same layout
__device__ unsigned short g_w2h[128 * 64];      // W2 hi bf16 (c2 keeps bf16 3-term)
__device__ unsigned short g_w2l[128 * 64];      // W2 lo bf16
__device__ unsigned short g_nodeh[(size_t)NNODE * 64];  // node fp16 rows
__device__ unsigned short g_edgeh[(size_t)NEDGE * 64];  // edge fp16 rows
__device__ float g_sumbuf[768];
__device__ float g_ab[768];

// ---------------- helpers ----------------
__device__ __forceinline__ float sigmoidf_(float x) { return 1.0f / (1.0f + __expf(-x)); }
__device__ __forceinline__ uint32_t smem_u32(const void* p) {
    uint32_t a;
    asm("{ .reg .u64 t; cvta.to.shared.u64 t, %1; cvt.u32.u64 %0, t; }" : "=r"(a) : "l"(p));
    return a;
}
__device__ __forceinline__ uint32_t bfpack(float f0, float f1) {   // f0 -> low half
    uint32_t r;
    asm("cvt.rn.bf16x2.f32 %0, %1, %2;" : "=r"(r) : "f"(f1), "f"(f0));
    return r;
}
__device__ __forceinline__ void cvt_pair(float f0, float f1, uint32_t& h, uint32_t& l) {
    h = bfpack(f0, f1);
    float r0 = f0 - __uint_as_float((h & 0xFFFFu) << 16);
    float r1 = f1 - __uint_as_float(h & 0xFFFF0000u);
    l = bfpack(r0, r1);
}
__device__ __forceinline__ void ldsm_x4(uint32_t addr, uint32_t* r) {
    asm volatile("ldmatrix.sync.aligned.m8n8.x4.shared.b16 {%0,%1,%2,%3}, [%4];"
        : "=r"(r[0]), "=r"(r[1]), "=r"(r[2]), "=r"(r[3]) : "r"(addr));
}
__device__ __forceinline__ void mma_bf16(float* c, const uint32_t* a, const uint32_t* b) {
    asm volatile("mma.sync.aligned.m16n8k16.row.col.f32.bf16.bf16.f32 "
        "{%0,%1,%2,%3}, {%4,%5,%6,%7}, {%8,%9}, {%0,%1,%2,%3};"
        : "+f"(c[0]), "+f"(c[1]), "+f"(c[2]), "+f"(c[3])
        : "r"(a[0]), "r"(a[1]), "r"(a[2]), "r"(a[3]), "r"(b[0]), "r"(b[1]));
}
__device__ __forceinline__ void mma_f16(float* c, const uint32_t* a, const uint32_t* b) {
    asm volatile("mma.sync.aligned.m16n8k16.row.col.f32.f16.f16.f32 "
        "{%0,%1,%2,%3}, {%4,%5,%6,%7}, {%8,%9}, {%0,%1,%2,%3};"
        : "+f"(c[0]), "+f"(c[1]), "+f"(c[2]), "+f"(c[3])
        : "r"(a[0]), "r"(a[1]), "r"(a[2]), "r"(a[3]), "r"(b[0]), "r"(b[1]));
}
__device__ __forceinline__ uint32_t a_addr(uint32_t base, int r0, int k0, int lane) {
    int row = r0 + (lane & 15);
    int kk = k0 + ((lane >> 4) << 3);
    return base + row * 128 + ((kk * 2) ^ ((row & 7) << 4));
}
__device__ __forceinline__ uint32_t b_addr(uint32_t base, int n0, int k0, int lane) {
    int row = n0 + (lane & 7) + ((lane >> 4) << 3);
    int kk = k0 + (((lane >> 3) & 1) << 3);
    return base + row * 128 + ((kk * 2) ^ ((row & 7) << 4));
}
__device__ __forceinline__ void cp16(uint32_t dst, const void* src, int sz) {
    asm volatile("cp.async.cg.shared.global [%0], [%1], 16, %2;"
                 :: "r"(dst), "l"(src), "r"(sz) : "memory");
}
#define CP_COMMIT() asm volatile("cp.async.commit_group;" ::: "memory")
#define CP_WAIT2()  asm volatile("cp.async.wait_group 2;" ::: "memory")

// c3 SMEM: W-hi [0,81920), W-lo ring 4x16K [81920,147456), A ring 4x16K [147456,212992)
#define SW_WL 81920
#define SW_A  147456
#define SMEM_C3 212992
// c2 SMEM: W2h [0,16K), W2l [16K,32K), A bufs x2 [32K, 96K)
#define SW2_A 32768
#define SMEM_C2 (SW2_A + 65536)        // 98304 B

// ============================================================================
// K0: combined prep — zero agg/sums, split W3 (fp16) and W2 (bf16)
// ============================================================================
__global__ void __launch_bounds__(256) k_prep(const float* __restrict__ W3,
                                              const float* __restrict__ W2) {
    size_t i = (size_t)blockIdx.x * 256 + threadIdx.x;
    size_t stride = (size_t)gridDim.x * 256;
    size_t nagg = (size_t)NEDGE * HE / 4;
    float4 z = make_float4(0.f, 0.f, 0.f, 0.f);
    float4* p4 = (float4*)g_agg;
    for (size_t p = i; p < nagg; p += stride) p4[p] = z;
    if (i < 768) g_sumbuf[i] = 0.0f;
    // W3 fp16 hi/lo split, panelized+swizzled (2-byte elements, layout unchanged)
    for (size_t idx = i; idx < 128 * 320; idx += stride) {
        int n = (int)(idx / 320), k = (int)(idx - (size_t)n * 320);
        float w = W3[idx];
        __half hb = __float2half_rn(w);
        __half lb = __float2half_rn(w - __half2float(hb));
        int p = k >> 6, kk = k & 63;
        uint32_t byte = (uint32_t)p * 16384u + (uint32_t)n * 128u + (uint32_t)((kk * 2) ^ ((n & 7) << 4));
        g_wbh[byte >> 1] = __half_as_ushort(hb);
        g_wbl[byte >> 1] = __half_as_ushort(lb);
    }
    // W2 bf16 split (c2 path unchanged)
    for (size_t idx = i; idx < 128 * 64; idx += stride) {
        int n = (int)(idx >> 6), k = (int)(idx & 63);
        float w = W2[idx];
        __nv_bfloat16 hb = __float2bfloat16_rn(w);
        __nv_bfloat16 lb = __float2bfloat16_rn(w - __bfloat162float(hb));
        uint32_t byte = (uint32_t)n * 128u + (uint32_t)((k * 2) ^ ((n & 7) << 4));
        g_w2h[byte >> 1] = __bfloat16_as_ushort(hb);
        g_w2l[byte >> 1] = __bfloat16_as_ushort(lb);
    }
}
// node/edge fp16 row images (hi only)
__global__ void __launch_bounds__(256) k_prepx(const float* __restrict__ node,
                                               const float* __restrict__ edge) {
    size_t i = (size_t)blockIdx.x * 256 + threadIdx.x;
    size_t stride = (size_t)gridDim.x * 256;
    const size_t nn = (size_t)NNODE * 16;
    const size_t ne = (size_t)NEDGE * 16;
    for (size_t p = i; p < nn + ne; p += stride) {
        float4 v = (p < nn) ? ((const float4*)node)[p] : ((const float4*)edge)[p - nn];
        __half2 h01 = __floats2half2_rn(v.x, v.y);
        __half2 h23 = __floats2half2_rn(v.z, v.w);
        uint2 pk = make_uint2(*(uint32_t*)&h01, *(uint32_t*)&h23);
        if (p < nn) ((uint2*)g_nodeh)[p] = pk;
        else        ((uint2*)g_edgeh)[p - nn] = pk;
    }
}

// ---------------- MMA panel bodies ----------------
// c3 fp16 2-term: A-hi only; W-hi (resident smem) + W-lo (ring smem)
__device__ __forceinline__ void mma_panelF(uint32_t abase, uint32_t wbh, uint32_t wbl,
                                           int wm, int wn, int lane, float acc[2][4][4]) {
#pragma unroll
    for (int ks = 0; ks < 4; ks++) {
        int k0 = ks * 16;
        uint32_t ah[2][4], bh[2][4], bl[2][4];
        ldsm_x4(a_addr(abase, wm * 32, k0, lane), ah[0]);
        ldsm_x4(a_addr(abase, wm * 32 + 16, k0, lane), ah[1]);
        ldsm_x4(b_addr(wbh, wn * 32, k0, lane), bh[0]);
        ldsm_x4(b_addr(wbh, wn * 32 + 16, k0, lane), bh[1]);
        ldsm_x4(b_addr(wbl, wn * 32, k0, lane), bl[0]);
        ldsm_x4(b_addr(wbl, wn * 32 + 16, k0, lane), bl[1]);
#pragma unroll
        for (int mt = 0; mt < 2; mt++)
#pragma unroll
            for (int g = 0; g < 2; g++) {
                mma_f16(acc[mt][2 * g],     ah[mt], &bh[g][0]);
                mma_f16(acc[mt][2 * g + 1], ah[mt], &bh[g][2]);
                mma_f16(acc[mt][2 * g],     ah[mt], &bl[g][0]);
                mma_f16(acc[mt][2 * g + 1], ah[mt], &bl[g][2]);
            }
    }
}
// c2 bf16 3-term (unchanged)
__device__ __forceinline__ void mma_panel8(uint32_t abase, uint32_t wbh, uint32_t wbl,
                                           int wm, int wn, int lane, float acc[2][4][4]) {
    uint32_t abl = abase + 16384;
#pragma unroll
    for (int ks = 0; ks < 4; ks++) {
        int k0 = ks * 16;
        uint32_t ah[2][4], al[2][4], bh[2][4], bl[2][4];
        ldsm_x4(a_addr(abase, wm * 32, k0, lane), ah[0]);
        ldsm_x4(a_addr(abase, wm * 32 + 16, k0, lane), ah[1]);
        ldsm_x4(a_addr(abl, wm * 32, k0, lane), al[0]);
        ldsm_x4(a_addr(abl, wm * 32 + 16, k0, lane), al[1]);
        ldsm_x4(b_addr(wbh, wn * 32, k0, lane), bh[0]);
        ldsm_x4(b_addr(wbh, wn * 32 + 16, k0, lane), bh[1]);
        ldsm_x4(b_addr(wbl, wn * 32, k0, lane), bl[0]);
        ldsm_x4(b_addr(wbl, wn * 32 + 16, k0, lane), bl[1]);
#pragma unroll
        for (int mt = 0; mt < 2; mt++)
#pragma unroll
            for (int g = 0; g < 2; g++) {
                mma_bf16(acc[mt][2 * g],     ah[mt], &bh[g][0]);
                mma_bf16(acc[mt][2 * g + 1], ah[mt], &bh[g][2]);
                mma_bf16(acc[mt][2 * g],     ah[mt], &bl[g][0]);
                mma_bf16(acc[mt][2 * g + 1], ah[mt], &bl[g][2]);
                mma_bf16(acc[mt][2 * g],     al[mt], &bh[g][0]);
                mma_bf16(acc[mt][2 * g + 1], al[mt], &bh[g][2]);
            }
    }
}

// ---------------- c3 async feeds (fp16, hi-only A) ----------------
__device__ __forceinline__ void issue_panel(const unsigned short* __restrict__ sh,
                                            const int* __restrict__ idx,
                                            int tbase, uint32_t abase, int tid) {
    int r = tid >> 2, q = tid & 3;
    int t = tbase + r;
    bool valid = (t < NTRI);
    int gi = valid ? idx[t] : 0;
    int sz = valid ? 16 : 0;
    const char* ph = (const char*)(sh + (size_t)gi * 64) + q * 32;
    int swm = (r & 7) << 4;
    uint32_t row = abase + (uint32_t)r * 128u;
    cp16(row + (uint32_t)((q * 32) ^ swm), ph, sz);
    cp16(row + (uint32_t)((q * 32 + 16) ^ swm), ph + 16, sz);
}
__device__ __forceinline__ void issue_wlo(int p, uint32_t dst, int tid) {
    const char* src = (const char*)g_wbl + p * 16384 + tid * 32;
    cp16(dst + (uint32_t)tid * 32u, src, 16);
    cp16(dst + (uint32_t)tid * 32u + 16u, src + 16, 16);
}

// ---------------- c2 gather (product path) ----------------
__device__ __forceinline__ void gather2p(const float* __restrict__ node,
                                         const int* __restrict__ vi,
                                         const int* __restrict__ vj,
                                         int tbase, int tid, float4* v) {
    int r = tid >> 2, q = tid & 3;
    int e = tbase + r;
    if (e < NEDGE) {
        const float4* a = (const float4*)(node + (size_t)vi[e] * 64) + q * 4;
        const float4* b = (const float4*)(node + (size_t)vj[e] * 64) + q * 4;
#pragma unroll
        for (int i = 0; i < 4; i++) {
            float4 x = a[i], y = b[i];
            v[i] = make_float4(x.x * y.x, x.y * y.y, x.z * y.z, x.w * y.w);
        }
    } else {
#pragma unroll
        for (int i = 0; i < 4; i++) v[i] = make_float4(0.f, 0.f, 0.f, 0.f);
    }
}
__device__ __forceinline__ void cvt_store4(const float4* v, char* buf, int tid) {
    int r = tid >> 2, q = tid & 3;
    int swm = (r & 7) << 4;
#pragma unroll
    for (int i = 0; i < 4; i++) {
        uint32_t h0, l0, h1, l1;
        cvt_pair(v[i].x, v[i].y, h0, l0);
        cvt_pair(v[i].z, v[i].w, h1, l1);
        int off = r * 128 + ((q * 32 + i * 8) ^ swm);
        *(uint2*)(buf + off) = make_uint2(h0, h1);
        *(uint2*)(buf + 16384 + off) = make_uint2(l0, l1);
    }
}

// ============================================================================
// K2: c3 linear — fp16 2-term, 4-buffer cp.async ring, wait_group 2
// ============================================================================
__global__ void __launch_bounds__(512, 1) k_c3mm(const int* __restrict__ ii,
                                                 const int* __restrict__ ij,
                                                 const int* __restrict__ ik,
                                                 const int* __restrict__ iji,
                                                 const int* __restrict__ ikj) {
    extern __shared__ __align__(128) char smal[];
    __shared__ float sred[256];
    const uint32_t sbal = smem_u32(smal);
    const int tid = threadIdx.x, wid = tid >> 5, lane = tid & 31;
    const int wm = wid >> 2, wn = wid & 3;
    {
        const uint4* srch = (const uint4*)g_wbh;
        uint4* dsth = (uint4*)smal;
        for (int i = tid; i < 5120; i += 512) dsth[i] = srch[i];
    }
    if (tid < 256) sred[tid] = 0.0f;
    __syncthreads();

    const int* idxs[5] = {ii, ij, ik, iji, ikj};

#define PREFETCH(G) do {                                                        \
        int _g = (G);                                                           \
        int _m = _g / 5, _p = _g - 5 * _m;                                      \
        int _tb = (blockIdx.x + _m * gridDim.x) * TILE_M;                       \
        const unsigned short* _sh = (_p < 3) ? g_nodeh : g_edgeh;               \
        uint32_t _buf = (uint32_t)(_g & 3);                                     \
        issue_panel(_sh, idxs[_p], _tb, sbal + SW_A + _buf * 16384u, tid);      \
        issue_wlo(_p, sbal + SW_WL + _buf * 16384u, tid);                       \
        CP_COMMIT();                                                            \
    } while (0)

    PREFETCH(0);
    PREFETCH(1);
    PREFETCH(2);

    const int lr = lane >> 2, lq = lane & 3;
    int gp = 0;
    for (int tile = blockIdx.x; tile < NT_TILES; tile += gridDim.x) {
        const int tbase = tile * TILE_M;
        float acc[2][4][4];
#pragma unroll
        for (int mt = 0; mt < 2; mt++)
#pragma unroll
            for (int nt = 0; nt < 4; nt++)
#pragma unroll
                for (int u = 0; u < 4; u++) acc[mt][nt][u] = 0.0f;

#pragma unroll
        for (int p = 0; p < 5; p++, gp++) {
            CP_WAIT2();
            __syncthreads();
            PREFETCH(gp + 3);
            uint32_t buf = (uint32_t)(gp & 3);
            mma_panelF(sbal + SW_A + buf * 16384u,
                       sbal + (uint32_t)p * 16384u,
                       sbal + SW_WL + buf * 16384u, wm, wn, lane, acc);
        }

        // epilogue: y3 stores + fused column stats
#pragma unroll
        for (int mt = 0; mt < 2; mt++) {
            int gr = tbase + wm * 32 + mt * 16 + lr;
#pragma unroll
            for (int nt = 0; nt < 4; nt++) {
                int col = wn * 32 + nt * 8 + lq * 2;
                if (gr < NTRI)
                    *(float2*)&g_y3[(size_t)gr * CC + col] = make_float2(acc[mt][nt][0], acc[mt][nt][1]);
                if (gr + 8 < NTRI)
                    *(float2*)&g_y3[(size_t)(gr + 8) * CC + col] = make_float2(acc[mt][nt][2], acc[mt][nt][3]);
            }
        }
        float sv[8], qv[8];
#pragma unroll
        for (int nt = 0; nt < 4; nt++)
#pragma unroll
            for (int j = 0; j < 2; j++) {
                float a0 = acc[0][nt][j], a1 = acc[0][nt][j + 2];
                float a2 = acc[1][nt][j], a3 = acc[1][nt][j + 2];
                sv[nt * 2 + j] = a0 + a1 + a2 + a3;
                qv[nt * 2 + j] = a0 * a0 + a1 * a1 + a2 * a2 + a3 * a3;
            }
#pragma unroll
        for (int i = 0; i < 8; i++) {
#pragma unroll
            for (int m = 4; m < 32; m <<= 1) {
                sv[i] += __shfl_xor_sync(0xffffffff, sv[i], m);
                qv[i] += __shfl_xor_sync(0xffffffff, qv[i], m);
            }
        }
        if (lane < 4) {
#pragma unroll
            for (int i = 0; i < 8; i++) {
                int col = wn * 32 + (i >> 1) * 8 + lane * 2 + (i & 1);
                atomicAdd(&sred[col], sv[i]);
                atomicAdd(&sred[128 + col], qv[i]);
            }
        }
    }
    __syncthreads();
    if (tid < 256) atomicAdd(&g_sumbuf[256 + tid], sred[tid]);
#undef PREFETCH
}

// ============================================================================
// K1: c2 linear — bf16 3-term, 512 threads, cross-tile double buffer
// ============================================================================
__global__ void __launch_bounds__(512, 1) k_c2mm(const float* __restrict__ node,
                                                 const int* __restrict__ vi,
                                                 const int* __restrict__ vj) {
    extern __shared__ __align__(128) char smal[];
    __shared__ float sred[256];
    const uint32_t sbal = smem_u32(smal);
    const int tid = threadIdx.x, wid = tid >> 5, lane = tid & 31;
    const int wm = wid >> 2, wn = wid & 3;
    {
        const uint4* srch = (const uint4*)g_w2h;
        const uint4* srcl = (const uint4*)g_w2l;
        uint4* dsth = (uint4*)smal;
        uint4* dstl = (uint4*)(smal + 16384);
        for (int i = tid; i < 1024; i += 512) { dsth[i] = srch[i]; dstl[i] = srcl[i]; }
    }
    if (tid < 256) sred[tid] = 0.0f;

    float4 v[4];
    int tile = blockIdx.x;
    if (tile < NE_TILES) {
        gather2p(node, vi, vj, tile * TILE_M, tid, v);
        cvt_store4(v, smal + SW2_A, tid);
    }
    __syncthreads();
    uint32_t parOff = 0;
    const int lr = lane >> 2, lq = lane & 3;

    for (; tile < NE_TILES; tile += gridDim.x) {
        const int tbase = tile * TILE_M;
        float acc[2][4][4];
#pragma unroll
        for (int mt = 0; mt < 2; mt++)
#pragma unroll
            for (int nt = 0; nt < 4; nt++)
#pragma unroll
                for (int u = 0; u < 4; u++) acc[mt][nt][u] = 0.0f;

        int ntile = tile + gridDim.x;
        if (ntile < NE_TILES) gather2p(node, vi, vj, ntile * TILE_M, tid, v);
        mma_panel8(sbal + SW2_A + parOff, sbal, sbal + 16384u, wm, wn, lane, acc);
        if (ntile < NE_TILES) cvt_store4(v, smal + SW2_A + (parOff ^ 32768u), tid);

#pragma unroll
        for (int mt = 0; mt < 2; mt++) {
            int gr = tbase + wm * 32 + mt * 16 + lr;
#pragma unroll
            for (int nt = 0; nt < 4; nt++) {
                int col = wn * 32 + nt * 8 + lq * 2;
                if (gr < NEDGE)
                    *(float2*)&g_y2[(size_t)gr * CC + col] = make_float2(acc[mt][nt][0], acc[mt][nt][1]);
                if (gr + 8 < NEDGE)
                    *(float2*)&g_y2[(size_t)(gr + 8) * CC + col] = make_float2(acc[mt][nt][2], acc[mt][nt][3]);
            }
        }
        float sv[8], qv[8];
#pragma unroll
        for (int nt = 0; nt < 4; nt++)
#pragma unroll
            for (int j = 0; j < 2; j++) {
                float a0 = acc[0][nt][j], a1 = acc[0][nt][j + 2];
                float a2 = acc[1][nt][j], a3 = acc[1][nt][j + 2];
                sv[nt * 2 + j] = a0 + a1 + a2 + a3;
                qv[nt * 2 + j] = a0 * a0 + a1 * a1 + a2 * a2 + a3 * a3;
            }
#pragma unroll
        for (int i = 0; i < 8; i++) {
#pragma unroll
            for (int m = 4; m < 32; m <<= 1) {
                sv[i] += __shfl_xor_sync(0xffffffff, sv[i], m);
                qv[i] += __shfl_xor_sync(0xffffffff, qv[i], m);
            }
        }
        if (lane < 4) {
#pragma unroll
            for (int i = 0; i < 8; i++) {
                int col = wn * 32 + (i >> 1) * 8 + lane * 2 + (i & 1);
                atomicAdd(&sred[col], sv[i]);
                atomicAdd(&sred[128 + col], qv[i]);
            }
        }
        __syncthreads();
        parOff ^= 32768u;
    }
    __syncthreads();
    if (tid < 256) atomicAdd(&g_sumbuf[tid], sred[tid]);
}

// ============================================================================
__global__ void k_stats1(const float* __restrict__ gc2, const float* __restrict__ bc2,
                         const float* __restrict__ gc3, const float* __restrict__ bc3) {
    int tid = threadIdx.x;  // 256
    if (tid < 128) {
        float mean = g_sumbuf[tid] * (1.0f / NEDGE);
        float var  = g_sumbuf[128 + tid] * (1.0f / NEDGE) - mean * mean;
        float a = gc2[tid] * rsqrtf(var + EPSF);
        g_ab[tid] = a;
        g_ab[128 + tid] = bc2[tid] - mean * a;
    } else {
        int c = tid - 128;
        float mean = g_sumbuf[256 + c] * (1.0f / NTRI);
        float var  = g_sumbuf[384 + c] * (1.0f / NTRI) - mean * mean;
        float a = gc3[c] * rsqrtf(var + EPSF);
        g_ab[256 + c] = a;
        g_ab[384 + c] = bc3[c] - mean * a;
    }
}

// ============================================================================
__global__ void __launch_bounds__(256) k_c2act() {
    __shared__ float sred[128];
    int tid = threadIdx.x;
    if (tid < 128) sred[tid] = 0.0f;
    __syncthreads();
    size_t i0 = (size_t)blockIdx.x * 256 + tid;
    int c = (int)(i0 & 15) * 4;
    float4 af = *(const float4*)&g_ab[c];
    float4 bf = *(const float4*)&g_ab[128 + c];
    float4 ac = *(const float4*)&g_ab[64 + c];
    float4 bc = *(const float4*)&g_ab[192 + c];
    float s[4] = {0, 0, 0, 0}, q[4] = {0, 0, 0, 0};
    size_t stride = (size_t)gridDim.x * 256;
    size_t n = (size_t)NEDGE * 16;
    for (size_t idx = i0; idx < n; idx += stride) {
        size_t e = idx >> 4;
        float4 yf = *(const float4*)&g_y2[(e << 7) + c];
        float4 yc = *(const float4*)&g_y2[(e << 7) + 64 + c];
        float4 g;
        g.x = sigmoidf_(yf.x * af.x + bf.x) * tanhf(yc.x * ac.x + bc.x);
        g.y = sigmoidf_(yf.y * af.y + bf.y) * tanhf(yc.y * ac.y + bc.y);
        g.z = sigmoidf_(yf.z * af.z + bf.z) * tanhf(yc.z * ac.z + bc.z);
        g.w = sigmoidf_(yf.w * af.w + bf.w) * tanhf(yc.w * ac.w + bc.w);
        *(float4*)&g_g2[idx << 2] = g;
        s[0] += g.x; s[1] += g.y; s[2] += g.z; s[3] += g.w;
        q[0] += g.x * g.x; q[1] += g.y * g.y; q[2] += g.z * g.z; q[3] += g.w * g.w;
    }
#pragma unroll
    for (int u = 0; u < 4; u++) {
        atomicAdd(&sred[c + u], s[u]);
        atomicAdd(&sred[64 + c + u], q[u]);
    }
    __syncthreads();
    if (tid < 128) atomicAdd(&g_sumbuf[512 + tid], sred[tid]);
}

// ============================================================================
__global__ void __launch_bounds__(256) k_c3act(const int* __restrict__ iji) {
    size_t i0 = (size_t)blockIdx.x * 256 + threadIdx.x;
    int c = (int)(i0 & 15) * 4;
    float4 af = *(const float4*)&g_ab[256 + c];
    float4 bf = *(const float4*)&g_ab[384 + c];
    float4 ac = *(const float4*)&g_ab[320 + c];
    float4 bc = *(const float4*)&g_ab[448 + c];
    size_t stride = (size_t)gridDim.x * 256;
    size_t n = (size_t)NTRI * 16;
    for (size_t idx = i0; idx < n; idx += stride) {
        size_t t = idx >> 4;
        float4 yf = *(const float4*)&g_y3[(t << 7) + c];
        float4 yc = *(const float4*)&g_y3[(t << 7) + 64 + c];
        float m0 = sigmoidf_(yf.x * af.x + bf.x) * tanhf(yc.x * ac.x + bc.x);
        float m1 = sigmoidf_(yf.y * af.y + bf.y) * tanhf(yc.y * ac.y + bc.y);
        float m2 = sigmoidf_(yf.z * af.z + bf.z) * tanhf(yc.z * ac.z + bc.z);
        float m3 = sigmoidf_(yf.w * af.w + bf.w) * tanhf(yc.w * ac.w + bc.w);
        float* dst = g_agg + ((size_t)iji[t] << 6) + c;
        asm volatile("red.global.v4.f32.add [%0], {%1, %2, %3, %4};"
                     :: "l"(dst), "f"(m0), "f"(m1), "f"(m2), "f"(m3) : "memory");
    }
}

// ============================================================================
__global__ void __launch_bounds__(256) k_aggstats() {
    __shared__ float sred[128];
    int tid = threadIdx.x;
    if (tid < 128) sred[tid] = 0.0f;
    __syncthreads();
    size_t i0 = (size_t)blockIdx.x * 256 + tid;
    int c = (int)(i0 & 15) * 4;
    float s[4] = {0, 0, 0, 0}, q[4] = {0, 0, 0, 0};
    size_t stride = (size_t)gridDim.x * 256;
    size_t n = (size_t)NEDGE * 16;
    for (size_t idx = i0; idx < n; idx += stride) {
        float4 vv = *(const float4*)&g_agg[idx << 2];
        s[0] += vv.x; s[1] += vv.y; s[2] += vv.z; s[3] += vv.w;
        q[0] += vv.x * vv.x; q[1] += vv.y * vv.y; q[2] += vv.z * vv.z; q[3] += vv.w * vv.w;
    }
#pragma unroll
    for (int u = 0; u < 4; u++) {
        atomicAdd(&sred[c + u], s[u]);
        atomicAdd(&sred[64 + c + u], q[u]);
    }
    __syncthreads();
    if (tid < 128) atomicAdd(&g_sumbuf[640 + tid], sred[tid]);
}

// ============================================================================
__global__ void k_stats2(const float* __restrict__ g22, const float* __restrict__ b22,
                         const float* __restrict__ g32, const float* __restrict__ b32) {
    int tid = threadIdx.x;  // 128
    if (tid < 64) {
        float mean = g_sumbuf[512 + tid] * (1.0f / NEDGE);
        float var  = g_sumbuf[576 + tid] * (1.0f / NEDGE) - mean * mean;
        float a = g22[tid] * rsqrtf(var + EPSF);
        g_ab[512 + tid] = a;
        g_ab[576 + tid] = b22[tid] - mean * a;
    } else {
        int c = tid - 64;
        float mean = g_sumbuf[640 + c] * (1.0f / NEDGE);
        float var  = g_sumbuf[704 + c] * (1.0f / NEDGE) - mean * mean;
        float a = g32[c] * rsqrtf(var + EPSF);
        g_ab[640 + c] = a;
        g_ab[704 + c] = b32[c] - mean * a;
    }
}

// ============================================================================
__global__ void __launch_bounds__(256) k_out(const float* __restrict__ edge,
                                             float* __restrict__ out) {
    size_t i0 = (size_t)blockIdx.x * 256 + threadIdx.x;
    int c = (int)(i0 & 15) * 4;
    float4 a2 = *(const float4*)&g_ab[512 + c];
    float4 b2v = *(const float4*)&g_ab[576 + c];
    float4 a3 = *(const float4*)&g_ab[640 + c];
    float4 b3v = *(const float4*)&g_ab[704 + c];
    size_t stride = (size_t)gridDim.x * 256;
    size_t n = (size_t)NEDGE * 16;
    for (size_t idx = i0; idx < n; idx += stride) {
        float4 e = *(const float4*)&edge[idx << 2];
        float4 g = *(const float4*)&g_g2[idx << 2];
        float4 a = *(const float4*)&g_agg[idx << 2];
        float4 o;
        o.x = tanhf(e.x + g.x * a2.x + b2v.x + a.x * a3.x + b3v.x);
        o.y = tanhf(e.y + g.y * a2.y + b2v.y + a.y * a3.y + b3v.y);
        o.z = tanhf(e.z + g.z * a2.z + b2v.z + a.z * a3.z + b3v.z);
        o.w = tanhf(e.w + g.w * a2.w + b2v.w + a.w * a3.w + b3v.w);
        *(float4*)&out[idx << 2] = o;
    }
}

// ============================================================================
extern "C" void kernel_launch(void* const* d_in, const int* in_sizes, int n_in,
                              void* d_out, int out_size) {
    const float* node = (const float*)d_in[0];
    const float* edge = (const float*)d_in[1];
    const int* vi     = (const int*)d_in[2];
    const int* vj     = (const int*)d_in[3];
    const int* idx_i  = (const int*)d_in[4];
    const int* idx_j  = (const int*)d_in[5];
    const int* idx_k  = (const int*)d_in[6];
    const int* idx_ji = (const int*)d_in[7];
    const int* idx_kj = (const int*)d_in[8];
    const float* W2   = (const float*)d_in[9];
    const float* W3   = (const float*)d_in[11];
    const float* gc2  = (const float*)d_in[13];
    const float* bc2  = (const float*)d_in[14];
    const float* gc3  = (const float*)d_in[15];
    const float* bc3  = (const float*)d_in[16];
    const float* g22  = (const float*)d_in[17];
    const float* b22  = (const float*)d_in[18];
    const float* g32  = (const float*)d_in[19];
    const float* b32  = (const float*)d_in[20];
    float* out = (float*)d_out;

    cudaFuncSetAttribute(k_c2mm, cudaFuncAttributeMaxDynamicSharedMemorySize, SMEM_C2);
    cudaFuncSetAttribute(k_c3mm, cudaFuncAttributeMaxDynamicSharedMemorySize, SMEM_C3);

    k_prep<<<1024, 256>>>(W3, W2);
    k_prepx<<<2048, 256>>>(node, edge);
    k_c3mm<<<148, 512, SMEM_C3>>>(idx_i, idx_j, idx_k, idx_ji, idx_kj);
    k_c2mm<<<148, 512, SMEM_C2>>>(node, vi, vj);
    k_stats1<<<1, 256>>>(gc2, bc2, gc3, bc3);
    k_c2act<<<512, 256>>>();
    k_c3act<<<2048, 256>>>(idx_ji);
    k_aggstats<<<512, 256>>>();
    k_stats2<<<1, 128>>>(g22, b22, g32, b32);
    k_out<<<512, 256>>>(edge, out);
}

// round 13
// speedup vs baseline: 1.3030x; 1.0134x over previous
#include <cuda_runtime.h>
#include <cuda_bf16.h>
#include <cuda_fp16.h>
#include <cstdint>
#include <math.h>

#define HN 64
#define HE 64
#define NNODE 50000
#define NEDGE 200000
#define NTRI  600000
#define CC 128
#define D3 320
#define EPSF 1e-5f
#define TILE_M 128
#define NT_TILES ((NTRI + TILE_M - 1) / TILE_M)   // 4688
#define NE_TILES ((NEDGE + TILE_M - 1) / TILE_M)  // 1563

// ---------------- scratch ----------------
__device__ float g_y2[(size_t)NEDGE * CC];
__device__ unsigned short g_y3h[(size_t)NTRI * CC];   // y3 as fp16
__device__ float g_g2[(size_t)NEDGE * HE];
__device__ float g_agg[(size_t)NEDGE * HE];
__device__ unsigned short g_wbh[128 * 320];     // W3 hi fp16, panelized+swizzled
__device__ unsigned short g_wbl[128 * 320];     // W3 lo fp16
__device__ unsigned short g_w2h[128 * 64];      // W2 hi bf16
__device__ unsigned short g_w2l[128 * 64];      // W2 lo bf16
__device__ unsigned short g_nodeh[(size_t)NNODE * 64];  // node fp16 rows
__device__ unsigned short g_edgeh[(size_t)NEDGE * 64];  // edge fp16 rows
__device__ float g_sumbuf[768];
__device__ float g_ab[768];

// ---------------- helpers ----------------
__device__ __forceinline__ float sigmoidf_(float x) { return 1.0f / (1.0f + __expf(-x)); }
__device__ __forceinline__ uint32_t smem_u32(const void* p) {
    uint32_t a;
    asm("{ .reg .u64 t; cvta.to.shared.u64 t, %1; cvt.u32.u64 %0, t; }" : "=r"(a) : "l"(p));
    return a;
}
__device__ __forceinline__ uint32_t bfpack(float f0, float f1) {   // f0 -> low half
    uint32_t r;
    asm("cvt.rn.bf16x2.f32 %0, %1, %2;" : "=r"(r) : "f"(f1), "f"(f0));
    return r;
}
__device__ __forceinline__ void cvt_pair(float f0, float f1, uint32_t& h, uint32_t& l) {
    h = bfpack(f0, f1);
    float r0 = f0 - __uint_as_float((h & 0xFFFFu) << 16);
    float r1 = f1 - __uint_as_float(h & 0xFFFF0000u);
    l = bfpack(r0, r1);
}
__device__ __forceinline__ void ldsm_x4(uint32_t addr, uint32_t* r) {
    asm volatile("ldmatrix.sync.aligned.m8n8.x4.shared.b16 {%0,%1,%2,%3}, [%4];"
        : "=r"(r[0]), "=r"(r[1]), "=r"(r[2]), "=r"(r[3]) : "r"(addr));
}
__device__ __forceinline__ void mma_bf16(float* c, const uint32_t* a, const uint32_t* b) {
    asm volatile("mma.sync.aligned.m16n8k16.row.col.f32.bf16.bf16.f32 "
        "{%0,%1,%2,%3}, {%4,%5,%6,%7}, {%8,%9}, {%0,%1,%2,%3};"
        : "+f"(c[0]), "+f"(c[1]), "+f"(c[2]), "+f"(c[3])
        : "r"(a[0]), "r"(a[1]), "r"(a[2]), "r"(a[3]), "r"(b[0]), "r"(b[1]));
}
__device__ __forceinline__ void mma_f16(float* c, const uint32_t* a, const uint32_t* b) {
    asm volatile("mma.sync.aligned.m16n8k16.row.col.f32.f16.f16.f32 "
        "{%0,%1,%2,%3}, {%4,%5,%6,%7}, {%8,%9}, {%0,%1,%2,%3};"
        : "+f"(c[0]), "+f"(c[1]), "+f"(c[2]), "+f"(c[3])
        : "r"(a[0]), "r"(a[1]), "r"(a[2]), "r"(a[3]), "r"(b[0]), "r"(b[1]));
}
__device__ __forceinline__ uint32_t a_addr(uint32_t base, int r0, int k0, int lane) {
    int row = r0 + (lane & 15);
    int kk = k0 + ((lane >> 4) << 3);
    return base + row * 128 + ((kk * 2) ^ ((row & 7) << 4));
}
__device__ __forceinline__ uint32_t b_addr(uint32_t base, int n0, int k0, int lane) {
    int row = n0 + (lane & 7) + ((lane >> 4) << 3);
    int kk = k0 + (((lane >> 3) & 1) << 3);
    return base + row * 128 + ((kk * 2) ^ ((row & 7) << 4));
}
__device__ __forceinline__ void cp16(uint32_t dst, const void* src, int sz) {
    asm volatile("cp.async.cg.shared.global [%0], [%1], 16, %2;"
                 :: "r"(dst), "l"(src), "r"(sz) : "memory");
}
#define CP_COMMIT() asm volatile("cp.async.commit_group;" ::: "memory")
#define CP_WAIT2()  asm volatile("cp.async.wait_group 2;" ::: "memory")

// c3 SMEM: W-hi [0,81920), W-lo ring 4x16K [81920,147456), A ring 4x16K [147456,212992)
#define SW_WL 81920
#define SW_A  147456
#define SMEM_C3 212992
// c2 SMEM: W2h [0,16K), W2l [16K,32K), A bufs x2 [32K, 96K)
#define SW2_A 32768
#define SMEM_C2 (SW2_A + 65536)        // 98304 B

// ============================================================================
// K0: combined prep — zero agg/sums, split W3 (fp16), W2 (bf16), node/edge (fp16)
// ============================================================================
__global__ void __launch_bounds__(256) k_prep(const float* __restrict__ W3,
                                              const float* __restrict__ W2,
                                              const float* __restrict__ node,
                                              const float* __restrict__ edge) {
    size_t i = (size_t)blockIdx.x * 256 + threadIdx.x;
    size_t stride = (size_t)gridDim.x * 256;
    size_t nagg = (size_t)NEDGE * HE / 4;
    float4 z = make_float4(0.f, 0.f, 0.f, 0.f);
    float4* p4 = (float4*)g_agg;
    for (size_t p = i; p < nagg; p += stride) p4[p] = z;
    if (i < 768) g_sumbuf[i] = 0.0f;
    // W3 fp16 hi/lo split, panelized+swizzled
    for (size_t idx = i; idx < 128 * 320; idx += stride) {
        int n = (int)(idx / 320), k = (int)(idx - (size_t)n * 320);
        float w = W3[idx];
        __half hb = __float2half_rn(w);
        __half lb = __float2half_rn(w - __half2float(hb));
        int p = k >> 6, kk = k & 63;
        uint32_t byte = (uint32_t)p * 16384u + (uint32_t)n * 128u + (uint32_t)((kk * 2) ^ ((n & 7) << 4));
        g_wbh[byte >> 1] = __half_as_ushort(hb);
        g_wbl[byte >> 1] = __half_as_ushort(lb);
    }
    // W2 bf16 split
    for (size_t idx = i; idx < 128 * 64; idx += stride) {
        int n = (int)(idx >> 6), k = (int)(idx & 63);
        float w = W2[idx];
        __nv_bfloat16 hb = __float2bfloat16_rn(w);
        __nv_bfloat16 lb = __float2bfloat16_rn(w - __bfloat162float(hb));
        uint32_t byte = (uint32_t)n * 128u + (uint32_t)((k * 2) ^ ((n & 7) << 4));
        g_w2h[byte >> 1] = __bfloat16_as_ushort(hb);
        g_w2l[byte >> 1] = __bfloat16_as_ushort(lb);
    }
    // node/edge fp16 row images
    const size_t nn = (size_t)NNODE * 16;
    const size_t ne = (size_t)NEDGE * 16;
    for (size_t p = i; p < nn + ne; p += stride) {
        float4 v = (p < nn) ? ((const float4*)node)[p] : ((const float4*)edge)[p - nn];
        __half2 h01 = __floats2half2_rn(v.x, v.y);
        __half2 h23 = __floats2half2_rn(v.z, v.w);
        uint2 pk = make_uint2(*(uint32_t*)&h01, *(uint32_t*)&h23);
        if (p < nn) ((uint2*)g_nodeh)[p] = pk;
        else        ((uint2*)g_edgeh)[p - nn] = pk;
    }
}

// ---------------- MMA panel bodies ----------------
// c3 fp16 2-term
__device__ __forceinline__ void mma_panelF(uint32_t abase, uint32_t wbh, uint32_t wbl,
                                           int wm, int wn, int lane, float acc[2][4][4]) {
#pragma unroll
    for (int ks = 0; ks < 4; ks++) {
        int k0 = ks * 16;
        uint32_t ah[2][4], bh[2][4], bl[2][4];
        ldsm_x4(a_addr(abase, wm * 32, k0, lane), ah[0]);
        ldsm_x4(a_addr(abase, wm * 32 + 16, k0, lane), ah[1]);
        ldsm_x4(b_addr(wbh, wn * 32, k0, lane), bh[0]);
        ldsm_x4(b_addr(wbh, wn * 32 + 16, k0, lane), bh[1]);
        ldsm_x4(b_addr(wbl, wn * 32, k0, lane), bl[0]);
        ldsm_x4(b_addr(wbl, wn * 32 + 16, k0, lane), bl[1]);
#pragma unroll
        for (int mt = 0; mt < 2; mt++)
#pragma unroll
            for (int g = 0; g < 2; g++) {
                mma_f16(acc[mt][2 * g],     ah[mt], &bh[g][0]);
                mma_f16(acc[mt][2 * g + 1], ah[mt], &bh[g][2]);
                mma_f16(acc[mt][2 * g],     ah[mt], &bl[g][0]);
                mma_f16(acc[mt][2 * g + 1], ah[mt], &bl[g][2]);
            }
    }
}
// c2 bf16 3-term
__device__ __forceinline__ void mma_panel8(uint32_t abase, uint32_t wbh, uint32_t wbl,
                                           int wm, int wn, int lane, float acc[2][4][4]) {
    uint32_t abl = abase + 16384;
#pragma unroll
    for (int ks = 0; ks < 4; ks++) {
        int k0 = ks * 16;
        uint32_t ah[2][4], al[2][4], bh[2][4], bl[2][4];
        ldsm_x4(a_addr(abase, wm * 32, k0, lane), ah[0]);
        ldsm_x4(a_addr(abase, wm * 32 + 16, k0, lane), ah[1]);
        ldsm_x4(a_addr(abl, wm * 32, k0, lane), al[0]);
        ldsm_x4(a_addr(abl, wm * 32 + 16, k0, lane), al[1]);
        ldsm_x4(b_addr(wbh, wn * 32, k0, lane), bh[0]);
        ldsm_x4(b_addr(wbh, wn * 32 + 16, k0, lane), bh[1]);
        ldsm_x4(b_addr(wbl, wn * 32, k0, lane), bl[0]);
        ldsm_x4(b_addr(wbl, wn * 32 + 16, k0, lane), bl[1]);
#pragma unroll
        for (int mt = 0; mt < 2; mt++)
#pragma unroll
            for (int g = 0; g < 2; g++) {
                mma_bf16(acc[mt][2 * g],     ah[mt], &bh[g][0]);
                mma_bf16(acc[mt][2 * g + 1], ah[mt], &bh[g][2]);
                mma_bf16(acc[mt][2 * g],     ah[mt], &bl[g][0]);
                mma_bf16(acc[mt][2 * g + 1], ah[mt], &bl[g][2]);
                mma_bf16(acc[mt][2 * g],     al[mt], &bh[g][0]);
                mma_bf16(acc[mt][2 * g + 1], al[mt], &bh[g][2]);
            }
    }
}

// ---------------- c3 async feeds ----------------
__device__ __forceinline__ void issue_panel(const unsigned short* __restrict__ sh,
                                            const int* __restrict__ idx,
                                            int tbase, uint32_t abase, int tid) {
    int r = tid >> 2, q = tid & 3;
    int t = tbase + r;
    bool valid = (t < NTRI);
    int gi = valid ? idx[t] : 0;
    int sz = valid ? 16 : 0;
    const char* ph = (const char*)(sh + (size_t)gi * 64) + q * 32;
    int swm = (r & 7) << 4;
    uint32_t row = abase + (uint32_t)r * 128u;
    cp16(row + (uint32_t)((q * 32) ^ swm), ph, sz);
    cp16(row + (uint32_t)((q * 32 + 16) ^ swm), ph + 16, sz);
}
__device__ __forceinline__ void issue_wlo(int p, uint32_t dst, int tid) {
    const char* src = (const char*)g_wbl + p * 16384 + tid * 32;
    cp16(dst + (uint32_t)tid * 32u, src, 16);
    cp16(dst + (uint32_t)tid * 32u + 16u, src + 16, 16);
}

// ---------------- c2 gather ----------------
__device__ __forceinline__ void gather2p(const float* __restrict__ node,
                                         const int* __restrict__ vi,
                                         const int* __restrict__ vj,
                                         int tbase, int tid, float4* v) {
    int r = tid >> 2, q = tid & 3;
    int e = tbase + r;
    if (e < NEDGE) {
        const float4* a = (const float4*)(node + (size_t)vi[e] * 64) + q * 4;
        const float4* b = (const float4*)(node + (size_t)vj[e] * 64) + q * 4;
#pragma unroll
        for (int i = 0; i < 4; i++) {
            float4 x = a[i], y = b[i];
            v[i] = make_float4(x.x * y.x, x.y * y.y, x.z * y.z, x.w * y.w);
        }
    } else {
#pragma unroll
        for (int i = 0; i < 4; i++) v[i] = make_float4(0.f, 0.f, 0.f, 0.f);
    }
}
__device__ __forceinline__ void cvt_store4(const float4* v, char* buf, int tid) {
    int r = tid >> 2, q = tid & 3;
    int swm = (r & 7) << 4;
#pragma unroll
    for (int i = 0; i < 4; i++) {
        uint32_t h0, l0, h1, l1;
        cvt_pair(v[i].x, v[i].y, h0, l0);
        cvt_pair(v[i].z, v[i].w, h1, l1);
        int off = r * 128 + ((q * 32 + i * 8) ^ swm);
        *(uint2*)(buf + off) = make_uint2(h0, h1);
        *(uint2*)(buf + 16384 + off) = make_uint2(l0, l1);
    }
}

// ============================================================================
// K2: c3 linear — fp16 2-term, 4-buffer cp.async ring, y3 stored fp16
// ============================================================================
__global__ void __launch_bounds__(512, 1) k_c3mm(const int* __restrict__ ii,
                                                 const int* __restrict__ ij,
                                                 const int* __restrict__ ik,
                                                 const int* __restrict__ iji,
                                                 const int* __restrict__ ikj) {
    extern __shared__ __align__(128) char smal[];
    __shared__ float sred[256];
    const uint32_t sbal = smem_u32(smal);
    const int tid = threadIdx.x, wid = tid >> 5, lane = tid & 31;
    const int wm = wid >> 2, wn = wid & 3;
    {
        const uint4* srch = (const uint4*)g_wbh;
        uint4* dsth = (uint4*)smal;
        for (int i = tid; i < 5120; i += 512) dsth[i] = srch[i];
    }
    if (tid < 256) sred[tid] = 0.0f;
    __syncthreads();

    const int* idxs[5] = {ii, ij, ik, iji, ikj};

#define PREFETCH(G) do {                                                        \
        int _g = (G);                                                           \
        int _m = _g / 5, _p = _g - 5 * _m;                                      \
        int _tb = (blockIdx.x + _m * gridDim.x) * TILE_M;                       \
        const unsigned short* _sh = (_p < 3) ? g_nodeh : g_edgeh;               \
        uint32_t _buf = (uint32_t)(_g & 3);                                     \
        issue_panel(_sh, idxs[_p], _tb, sbal + SW_A + _buf * 16384u, tid);      \
        issue_wlo(_p, sbal + SW_WL + _buf * 16384u, tid);                       \
        CP_COMMIT();                                                            \
    } while (0)

    PREFETCH(0);
    PREFETCH(1);
    PREFETCH(2);

    const int lr = lane >> 2, lq = lane & 3;
    int gp = 0;
    for (int tile = blockIdx.x; tile < NT_TILES; tile += gridDim.x) {
        const int tbase = tile * TILE_M;
        float acc[2][4][4];
#pragma unroll
        for (int mt = 0; mt < 2; mt++)
#pragma unroll
            for (int nt = 0; nt < 4; nt++)
#pragma unroll
                for (int u = 0; u < 4; u++) acc[mt][nt][u] = 0.0f;

#pragma unroll
        for (int p = 0; p < 5; p++, gp++) {
            CP_WAIT2();
            __syncthreads();
            PREFETCH(gp + 3);
            uint32_t buf = (uint32_t)(gp & 3);
            mma_panelF(sbal + SW_A + buf * 16384u,
                       sbal + (uint32_t)p * 16384u,
                       sbal + SW_WL + buf * 16384u, wm, wn, lane, acc);
        }

        // epilogue: y3 (fp16) stores + fused fp32 column stats
#pragma unroll
        for (int mt = 0; mt < 2; mt++) {
            int gr = tbase + wm * 32 + mt * 16 + lr;
#pragma unroll
            for (int nt = 0; nt < 4; nt++) {
                int col = wn * 32 + nt * 8 + lq * 2;
                __half2 v0 = __floats2half2_rn(acc[mt][nt][0], acc[mt][nt][1]);
                __half2 v1 = __floats2half2_rn(acc[mt][nt][2], acc[mt][nt][3]);
                if (gr < NTRI)
                    *(uint32_t*)&g_y3h[(size_t)gr * CC + col] = *(uint32_t*)&v0;
                if (gr + 8 < NTRI)
                    *(uint32_t*)&g_y3h[(size_t)(gr + 8) * CC + col] = *(uint32_t*)&v1;
            }
        }
        float sv[8], qv[8];
#pragma unroll
        for (int nt = 0; nt < 4; nt++)
#pragma unroll
            for (int j = 0; j < 2; j++) {
                float a0 = acc[0][nt][j], a1 = acc[0][nt][j + 2];
                float a2 = acc[1][nt][j], a3 = acc[1][nt][j + 2];
                sv[nt * 2 + j] = a0 + a1 + a2 + a3;
                qv[nt * 2 + j] = a0 * a0 + a1 * a1 + a2 * a2 + a3 * a3;
            }
#pragma unroll
        for (int i = 0; i < 8; i++) {
#pragma unroll
            for (int m = 4; m < 32; m <<= 1) {
                sv[i] += __shfl_xor_sync(0xffffffff, sv[i], m);
                qv[i] += __shfl_xor_sync(0xffffffff, qv[i], m);
            }
        }
        if (lane < 4) {
#pragma unroll
            for (int i = 0; i < 8; i++) {
                int col = wn * 32 + (i >> 1) * 8 + lane * 2 + (i & 1);
                atomicAdd(&sred[col], sv[i]);
                atomicAdd(&sred[128 + col], qv[i]);
            }
        }
    }
    __syncthreads();
    if (tid < 256) atomicAdd(&g_sumbuf[256 + tid], sred[tid]);
#undef PREFETCH
}

// ============================================================================
// K1: c2 linear — bf16 3-term, 512 threads, cross-tile double buffer
// ============================================================================
__global__ void __launch_bounds__(512, 1) k_c2mm(const float* __restrict__ node,
                                                 const int* __restrict__ vi,
                                                 const int* __restrict__ vj) {
    extern __shared__ __align__(128) char smal[];
    __shared__ float sred[256];
    const uint32_t sbal = smem_u32(smal);
    const int tid = threadIdx.x, wid = tid >> 5, lane = tid & 31;
    const int wm = wid >> 2, wn = wid & 3;
    {
        const uint4* srch = (const uint4*)g_w2h;
        const uint4* srcl = (const uint4*)g_w2l;
        uint4* dsth = (uint4*)smal;
        uint4* dstl = (uint4*)(smal + 16384);
        for (int i = tid; i < 1024; i += 512) { dsth[i] = srch[i]; dstl[i] = srcl[i]; }
    }
    if (tid < 256) sred[tid] = 0.0f;

    float4 v[4];
    int tile = blockIdx.x;
    if (tile < NE_TILES) {
        gather2p(node, vi, vj, tile * TILE_M, tid, v);
        cvt_store4(v, smal + SW2_A, tid);
    }
    __syncthreads();
    uint32_t parOff = 0;
    const int lr = lane >> 2, lq = lane & 3;

    for (; tile < NE_TILES; tile += gridDim.x) {
        const int tbase = tile * TILE_M;
        float acc[2][4][4];
#pragma unroll
        for (int mt = 0; mt < 2; mt++)
#pragma unroll
            for (int nt = 0; nt < 4; nt++)
#pragma unroll
                for (int u = 0; u < 4; u++) acc[mt][nt][u] = 0.0f;

        int ntile = tile + gridDim.x;
        if (ntile < NE_TILES) gather2p(node, vi, vj, ntile * TILE_M, tid, v);
        mma_panel8(sbal + SW2_A + parOff, sbal, sbal + 16384u, wm, wn, lane, acc);
        if (ntile < NE_TILES) cvt_store4(v, smal + SW2_A + (parOff ^ 32768u), tid);

#pragma unroll
        for (int mt = 0; mt < 2; mt++) {
            int gr = tbase + wm * 32 + mt * 16 + lr;
#pragma unroll
            for (int nt = 0; nt < 4; nt++) {
                int col = wn * 32 + nt * 8 + lq * 2;
                if (gr < NEDGE)
                    *(float2*)&g_y2[(size_t)gr * CC + col] = make_float2(acc[mt][nt][0], acc[mt][nt][1]);
                if (gr + 8 < NEDGE)
                    *(float2*)&g_y2[(size_t)(gr + 8) * CC + col] = make_float2(acc[mt][nt][2], acc[mt][nt][3]);
            }
        }
        float sv[8], qv[8];
#pragma unroll
        for (int nt = 0; nt < 4; nt++)
#pragma unroll
            for (int j = 0; j < 2; j++) {
                float a0 = acc[0][nt][j], a1 = acc[0][nt][j + 2];
                float a2 = acc[1][nt][j], a3 = acc[1][nt][j + 2];
                sv[nt * 2 + j] = a0 + a1 + a2 + a3;
                qv[nt * 2 + j] = a0 * a0 + a1 * a1 + a2 * a2 + a3 * a3;
            }
#pragma unroll
        for (int i = 0; i < 8; i++) {
#pragma unroll
            for (int m = 4; m < 32; m <<= 1) {
                sv[i] += __shfl_xor_sync(0xffffffff, sv[i], m);
                qv[i] += __shfl_xor_sync(0xffffffff, qv[i], m);
            }
        }
        if (lane < 4) {
#pragma unroll
            for (int i = 0; i < 8; i++) {
                int col = wn * 32 + (i >> 1) * 8 + lane * 2 + (i & 1);
                atomicAdd(&sred[col], sv[i]);
                atomicAdd(&sred[128 + col], qv[i]);
            }
        }
        __syncthreads();
        parOff ^= 32768u;
    }
    __syncthreads();
    if (tid < 256) atomicAdd(&g_sumbuf[tid], sred[tid]);
}

// ============================================================================
__global__ void k_stats1(const float* __restrict__ gc2, const float* __restrict__ bc2,
                         const float* __restrict__ gc3, const float* __restrict__ bc3) {
    int tid = threadIdx.x;  // 256
    if (tid < 128) {
        float mean = g_sumbuf[tid] * (1.0f / NEDGE);
        float var  = g_sumbuf[128 + tid] * (1.0f / NEDGE) - mean * mean;
        float a = gc2[tid] * rsqrtf(var + EPSF);
        g_ab[tid] = a;
        g_ab[128 + tid] = bc2[tid] - mean * a;
    } else {
        int c = tid - 128;
        float mean = g_sumbuf[256 + c] * (1.0f / NTRI);
        float var  = g_sumbuf[384 + c] * (1.0f / NTRI) - mean * mean;
        float a = gc3[c] * rsqrtf(var + EPSF);
        g_ab[256 + c] = a;
        g_ab[384 + c] = bc3[c] - mean * a;
    }
}

// ============================================================================
__global__ void __launch_bounds__(256) k_c2act() {
    __shared__ float sred[128];
    int tid = threadIdx.x;
    if (tid < 128) sred[tid] = 0.0f;
    __syncthreads();
    size_t i0 = (size_t)blockIdx.x * 256 + tid;
    int c = (int)(i0 & 15) * 4;
    float4 af = *(const float4*)&g_ab[c];
    float4 bf = *(const float4*)&g_ab[128 + c];
    float4 ac = *(const float4*)&g_ab[64 + c];
    float4 bc = *(const float4*)&g_ab[192 + c];
    float s[4] = {0, 0, 0, 0}, q[4] = {0, 0, 0, 0};
    size_t stride = (size_t)gridDim.x * 256;
    size_t n = (size_t)NEDGE * 16;
    for (size_t idx = i0; idx < n; idx += stride) {
        size_t e = idx >> 4;
        float4 yf = *(const float4*)&g_y2[(e << 7) + c];
        float4 yc = *(const float4*)&g_y2[(e << 7) + 64 + c];
        float4 g;
        g.x = sigmoidf_(yf.x * af.x + bf.x) * tanhf(yc.x * ac.x + bc.x);
        g.y = sigmoidf_(yf.y * af.y + bf.y) * tanhf(yc.y * ac.y + bc.y);
        g.z = sigmoidf_(yf.z * af.z + bf.z) * tanhf(yc.z * ac.z + bc.z);
        g.w = sigmoidf_(yf.w * af.w + bf.w) * tanhf(yc.w * ac.w + bc.w);
        *(float4*)&g_g2[idx << 2] = g;
        s[0] += g.x; s[1] += g.y; s[2] += g.z; s[3] += g.w;
        q[0] += g.x * g.x; q[1] += g.y * g.y; q[2] += g.z * g.z; q[3] += g.w * g.w;
    }
#pragma unroll
    for (int u = 0; u < 4; u++) {
        atomicAdd(&sred[c + u], s[u]);
        atomicAdd(&sred[64 + c + u], q[u]);
    }
    __syncthreads();
    if (tid < 128) atomicAdd(&g_sumbuf[512 + tid], sred[tid]);
}

// ============================================================================
// K5: c3 activation + scatter, reads fp16 y3
// ============================================================================
__global__ void __launch_bounds__(256) k_c3act(const int* __restrict__ iji) {
    size_t i0 = (size_t)blockIdx.x * 256 + threadIdx.x;
    int c = (int)(i0 & 15) * 4;
    float4 af = *(const float4*)&g_ab[256 + c];
    float4 bf = *(const float4*)&g_ab[384 + c];
    float4 ac = *(const float4*)&g_ab[320 + c];
    float4 bc = *(const float4*)&g_ab[448 + c];
    size_t stride = (size_t)gridDim.x * 256;
    size_t n = (size_t)NTRI * 16;
    for (size_t idx = i0; idx < n; idx += stride) {
        size_t t = idx >> 4;
        uint2 pf = *(const uint2*)&g_y3h[(t << 7) + c];
        uint2 pc = *(const uint2*)&g_y3h[(t << 7) + 64 + c];
        float2 f01 = __half22float2(*(__half2*)&pf.x);
        float2 f23 = __half22float2(*(__half2*)&pf.y);
        float2 c01 = __half22float2(*(__half2*)&pc.x);
        float2 c23 = __half22float2(*(__half2*)&pc.y);
        float m0 = sigmoidf_(f01.x * af.x + bf.x) * tanhf(c01.x * ac.x + bc.x);
        float m1 = sigmoidf_(f01.y * af.y + bf.y) * tanhf(c01.y * ac.y + bc.y);
        float m2 = sigmoidf_(f23.x * af.z + bf.z) * tanhf(c23.x * ac.z + bc.z);
        float m3 = sigmoidf_(f23.y * af.w + bf.w) * tanhf(c23.y * ac.w + bc.w);
        float* dst = g_agg + ((size_t)iji[t] << 6) + c;
        asm volatile("red.global.v4.f32.add [%0], {%1, %2, %3, %4};"
                     :: "l"(dst), "f"(m0), "f"(m1), "f"(m2), "f"(m3) : "memory");
    }
}

// ============================================================================
__global__ void __launch_bounds__(256) k_aggstats() {
    __shared__ float sred[128];
    int tid = threadIdx.x;
    if (tid < 128) sred[tid] = 0.0f;
    __syncthreads();
    size_t i0 = (size_t)blockIdx.x * 256 + tid;
    int c = (int)(i0 & 15) * 4;
    float s[4] = {0, 0, 0, 0}, q[4] = {0, 0, 0, 0};
    size_t stride = (size_t)gridDim.x * 256;
    size_t n = (size_t)NEDGE * 16;
    for (size_t idx = i0; idx < n; idx += stride) {
        float4 vv = *(const float4*)&g_agg[idx << 2];
        s[0] += vv.x; s[1] += vv.y; s[2] += vv.z; s[3] += vv.w;
        q[0] += vv.x * vv.x; q[1] += vv.y * vv.y; q[2] += vv.z * vv.z; q[3] += vv.w * vv.w;
    }
#pragma unroll
    for (int u = 0; u < 4; u++) {
        atomicAdd(&sred[c + u], s[u]);
        atomicAdd(&sred[64 + c + u], q[u]);
    }
    __syncthreads();
    if (tid < 128) atomicAdd(&g_sumbuf[640 + tid], sred[tid]);
}

// ============================================================================
__global__ void k_stats2(const float* __restrict__ g22, const float* __restrict__ b22,
                         const float* __restrict__ g32, const float* __restrict__ b32) {
    int tid = threadIdx.x;  // 128
    if (tid < 64) {
        float mean = g_sumbuf[512 + tid] * (1.0f / NEDGE);
        float var  = g_sumbuf[576 + tid] * (1.0f / NEDGE) - mean * mean;
        float a = g22[tid] * rsqrtf(var + EPSF);
        g_ab[512 + tid] = a;
        g_ab[576 + tid] = b22[tid] - mean * a;
    } else {
        int c = tid - 64;
        float mean = g_sumbuf[640 + c] * (1.0f / NEDGE);
        float var  = g_sumbuf[704 + c] * (1.0f / NEDGE) - mean * mean;
        float a = g32[c] * rsqrtf(var + EPSF);
        g_ab[640 + c] = a;
        g_ab[704 + c] = b32[c] - mean * a;
    }
}

// ============================================================================
__global__ void __launch_bounds__(256) k_out(const float* __restrict__ edge,
                                             float* __restrict__ out) {
    size_t i0 = (size_t)blockIdx.x * 256 + threadIdx.x;
    int c = (int)(i0 & 15) * 4;
    float4 a2 = *(const float4*)&g_ab[512 + c];
    float4 b2v = *(const float4*)&g_ab[576 + c];
    float4 a3 = *(const float4*)&g_ab[640 + c];
    float4 b3v = *(const float4*)&g_ab[704 + c];
    size_t stride = (size_t)gridDim.x * 256;
    size_t n = (size_t)NEDGE * 16;
    for (size_t idx = i0; idx < n; idx += stride) {
        float4 e = *(const float4*)&edge[idx << 2];
        float4 g = *(const float4*)&g_g2[idx << 2];
        float4 a = *(const float4*)&g_agg[idx << 2];
        float4 o;
        o.x = tanhf(e.x + g.x * a2.x + b2v.x + a.x * a3.x + b3v.x);
        o.y = tanhf(e.y + g.y * a2.y + b2v.y + a.y * a3.y + b3v.y);
        o.z = tanhf(e.z + g.z * a2.z + b2v.z + a.z * a3.z + b3v.z);
        o.w = tanhf(e.w + g.w * a2.w + b2v.w + a.w * a3.w + b3v.w);
        *(float4*)&out[idx << 2] = o;
    }
}

// ============================================================================
extern "C" void kernel_launch(void* const* d_in, const int* in_sizes, int n_in,
                              void* d_out, int out_size) {
    const float* node = (const float*)d_in[0];
    const float* edge = (const float*)d_in[1];
    const int* vi     = (const int*)d_in[2];
    const int* vj     = (const int*)d_in[3];
    const int* idx_i  = (const int*)d_in[4];
    const int* idx_j  = (const int*)d_in[5];
    const int* idx_k  = (const int*)d_in[6];
    const int* idx_ji = (const int*)d_in[7];
    const int* idx_kj = (const int*)d_in[8];
    const float* W2   = (const float*)d_in[9];
    const float* W3   = (const float*)d_in[11];
    const float* gc2  = (const float*)d_in[13];
    const float* bc2  = (const float*)d_in[14];
    const float* gc3  = (const float*)d_in[15];
    const float* bc3  = (const float*)d_in[16];
    const float* g22  = (const float*)d_in[17];
    const float* b22  = (const float*)d_in[18];
    const float* g32  = (const float*)d_in[19];
    const float* b32  = (const float*)d_in[20];
    float* out = (float*)d_out;

    cudaFuncSetAttribute(k_c2mm, cudaFuncAttributeMaxDynamicSharedMemorySize, SMEM_C2);
    cudaFuncSetAttribute(k_c3mm, cudaFuncAttributeMaxDynamicSharedMemorySize, SMEM_C3);

    k_prep<<<2048, 256>>>(W3, W2, node, edge);
    k_c3mm<<<148, 512, SMEM_C3>>>(idx_i, idx_j, idx_k, idx_ji, idx_kj);
    k_c2mm<<<148, 512, SMEM_C2>>>(node, vi, vj);
    k_stats1<<<1, 256>>>(gc2, bc2, gc3, bc3);
    k_c2act<<<512, 256>>>();
    k_c3act<<<2048, 256>>>(idx_ji);
    k_aggstats<<<512, 256>>>();
    k_stats2<<<1, 128>>>(g22, b22, g32, b32);
    k_out<<<512, 256>>>(edge, out);
}

// round 14
// speedup vs baseline: 1.3759x; 1.0559x over previous
#include <cuda_runtime.h>
#include <cuda_bf16.h>
#include <cuda_fp16.h>
#include <cstdint>
#include <math.h>

#define HN 64
#define HE 64
#define NNODE 50000
#define NEDGE 200000
#define NTRI  600000
#define CC 128
#define D3 320
#define EPSF 1e-5f
#define TILE_M 128
#define TILE_M3 256
#define NT_TILES ((NTRI + TILE_M3 - 1) / TILE_M3)  // 2344
#define NE_TILES ((NEDGE + TILE_M - 1) / TILE_M)   // 1563

// ---------------- scratch ----------------
__device__ float g_y2[(size_t)NEDGE * CC];
__device__ unsigned short g_y3h[(size_t)NTRI * CC];   // y3 as fp16
__device__ float g_g2[(size_t)NEDGE * HE];
__device__ float g_agg[(size_t)NEDGE * HE];
__device__ unsigned short g_wbh[128 * 320];     // W3 hi fp16, panelized+swizzled
__device__ unsigned short g_wbl[128 * 320];     // W3 lo fp16
__device__ unsigned short g_w2h[128 * 64];      // W2 hi bf16
__device__ unsigned short g_w2l[128 * 64];      // W2 lo bf16
__device__ unsigned short g_nodeh[(size_t)NNODE * 64];  // node fp16 rows
__device__ unsigned short g_edgeh[(size_t)NEDGE * 64];  // edge fp16 rows
__device__ float g_sumbuf[768];
__device__ float g_ab[768];

// ---------------- helpers ----------------
__device__ __forceinline__ float sigmoidf_(float x) { return 1.0f / (1.0f + __expf(-x)); }
__device__ __forceinline__ uint32_t smem_u32(const void* p) {
    uint32_t a;
    asm("{ .reg .u64 t; cvta.to.shared.u64 t, %1; cvt.u32.u64 %0, t; }" : "=r"(a) : "l"(p));
    return a;
}
__device__ __forceinline__ uint32_t bfpack(float f0, float f1) {   // f0 -> low half
    uint32_t r;
    asm("cvt.rn.bf16x2.f32 %0, %1, %2;" : "=r"(r) : "f"(f1), "f"(f0));
    return r;
}
__device__ __forceinline__ void cvt_pair(float f0, float f1, uint32_t& h, uint32_t& l) {
    h = bfpack(f0, f1);
    float r0 = f0 - __uint_as_float((h & 0xFFFFu) << 16);
    float r1 = f1 - __uint_as_float(h & 0xFFFF0000u);
    l = bfpack(r0, r1);
}
__device__ __forceinline__ void ldsm_x4(uint32_t addr, uint32_t* r) {
    asm volatile("ldmatrix.sync.aligned.m8n8.x4.shared.b16 {%0,%1,%2,%3}, [%4];"
        : "=r"(r[0]), "=r"(r[1]), "=r"(r[2]), "=r"(r[3]) : "r"(addr));
}
__device__ __forceinline__ void mma_bf16(float* c, const uint32_t* a, const uint32_t* b) {
    asm volatile("mma.sync.aligned.m16n8k16.row.col.f32.bf16.bf16.f32 "
        "{%0,%1,%2,%3}, {%4,%5,%6,%7}, {%8,%9}, {%0,%1,%2,%3};"
        : "+f"(c[0]), "+f"(c[1]), "+f"(c[2]), "+f"(c[3])
        : "r"(a[0]), "r"(a[1]), "r"(a[2]), "r"(a[3]), "r"(b[0]), "r"(b[1]));
}
__device__ __forceinline__ void mma_f16(float* c, const uint32_t* a, const uint32_t* b) {
    asm volatile("mma.sync.aligned.m16n8k16.row.col.f32.f16.f16.f32 "
        "{%0,%1,%2,%3}, {%4,%5,%6,%7}, {%8,%9}, {%0,%1,%2,%3};"
        : "+f"(c[0]), "+f"(c[1]), "+f"(c[2]), "+f"(c[3])
        : "r"(a[0]), "r"(a[1]), "r"(a[2]), "r"(a[3]), "r"(b[0]), "r"(b[1]));
}
__device__ __forceinline__ uint32_t a_addr(uint32_t base, int r0, int k0, int lane) {
    int row = r0 + (lane & 15);
    int kk = k0 + ((lane >> 4) << 3);
    return base + row * 128 + ((kk * 2) ^ ((row & 7) << 4));
}
__device__ __forceinline__ uint32_t b_addr(uint32_t base, int n0, int k0, int lane) {
    int row = n0 + (lane & 7) + ((lane >> 4) << 3);
    int kk = k0 + (((lane >> 3) & 1) << 3);
    return base + row * 128 + ((kk * 2) ^ ((row & 7) << 4));
}
__device__ __forceinline__ void cp16(uint32_t dst, const void* src, int sz) {
    asm volatile("cp.async.cg.shared.global [%0], [%1], 16, %2;"
                 :: "r"(dst), "l"(src), "r"(sz) : "memory");
}
#define CP_COMMIT() asm volatile("cp.async.commit_group;" ::: "memory")
#define CP_WAIT1()  asm volatile("cp.async.wait_group 1;" ::: "memory")

// c3 SMEM: W-hi [0,81920), W-lo ring 3x16K [81920,131072), A ring 3x32K [131072,229376)
#define SW_WL 81920
#define SW_A  131072
#define SMEM_C3 229376
// c2 SMEM: W2h [0,16K), W2l [16K,32K), A bufs x2 [32K, 96K)
#define SW2_A 32768
#define SMEM_C2 (SW2_A + 65536)        // 98304 B

// ============================================================================
// K0: combined prep — zero agg/sums, split W3 (fp16), W2 (bf16), node/edge (fp16)
// ============================================================================
__global__ void __launch_bounds__(256) k_prep(const float* __restrict__ W3,
                                              const float* __restrict__ W2,
                                              const float* __restrict__ node,
                                              const float* __restrict__ edge) {
    size_t i = (size_t)blockIdx.x * 256 + threadIdx.x;
    size_t stride = (size_t)gridDim.x * 256;
    size_t nagg = (size_t)NEDGE * HE / 4;
    float4 z = make_float4(0.f, 0.f, 0.f, 0.f);
    float4* p4 = (float4*)g_agg;
    for (size_t p = i; p < nagg; p += stride) p4[p] = z;
    if (i < 768) g_sumbuf[i] = 0.0f;
    for (size_t idx = i; idx < 128 * 320; idx += stride) {
        int n = (int)(idx / 320), k = (int)(idx - (size_t)n * 320);
        float w = W3[idx];
        __half hb = __float2half_rn(w);
        __half lb = __float2half_rn(w - __half2float(hb));
        int p = k >> 6, kk = k & 63;
        uint32_t byte = (uint32_t)p * 16384u + (uint32_t)n * 128u + (uint32_t)((kk * 2) ^ ((n & 7) << 4));
        g_wbh[byte >> 1] = __half_as_ushort(hb);
        g_wbl[byte >> 1] = __half_as_ushort(lb);
    }
    for (size_t idx = i; idx < 128 * 64; idx += stride) {
        int n = (int)(idx >> 6), k = (int)(idx & 63);
        float w = W2[idx];
        __nv_bfloat16 hb = __float2bfloat16_rn(w);
        __nv_bfloat16 lb = __float2bfloat16_rn(w - __bfloat162float(hb));
        uint32_t byte = (uint32_t)n * 128u + (uint32_t)((k * 2) ^ ((n & 7) << 4));
        g_w2h[byte >> 1] = __bfloat16_as_ushort(hb);
        g_w2l[byte >> 1] = __bfloat16_as_ushort(lb);
    }
    const size_t nn = (size_t)NNODE * 16;
    const size_t ne = (size_t)NEDGE * 16;
    for (size_t p = i; p < nn + ne; p += stride) {
        float4 v = (p < nn) ? ((const float4*)node)[p] : ((const float4*)edge)[p - nn];
        __half2 h01 = __floats2half2_rn(v.x, v.y);
        __half2 h23 = __floats2half2_rn(v.z, v.w);
        uint2 pk = make_uint2(*(uint32_t*)&h01, *(uint32_t*)&h23);
        if (p < nn) ((uint2*)g_nodeh)[p] = pk;
        else        ((uint2*)g_edgeh)[p - nn] = pk;
    }
}

// ---------------- MMA panel bodies ----------------
// c3 fp16 2-term, warp tile 64x32 (acc[4][4][4])
__device__ __forceinline__ void mma_panelD(uint32_t abase, uint32_t wbh, uint32_t wbl,
                                           int wm, int wn, int lane, float acc[4][4][4]) {
#pragma unroll
    for (int ks = 0; ks < 4; ks++) {
        int k0 = ks * 16;
        uint32_t ah[4][4], bh[2][4], bl[2][4];
#pragma unroll
        for (int mt = 0; mt < 4; mt++)
            ldsm_x4(a_addr(abase, wm * 64 + mt * 16, k0, lane), ah[mt]);
        ldsm_x4(b_addr(wbh, wn * 32, k0, lane), bh[0]);
        ldsm_x4(b_addr(wbh, wn * 32 + 16, k0, lane), bh[1]);
        ldsm_x4(b_addr(wbl, wn * 32, k0, lane), bl[0]);
        ldsm_x4(b_addr(wbl, wn * 32 + 16, k0, lane), bl[1]);
#pragma unroll
        for (int mt = 0; mt < 4; mt++)
#pragma unroll
            for (int g = 0; g < 2; g++) {
                mma_f16(acc[mt][2 * g],     ah[mt], &bh[g][0]);
                mma_f16(acc[mt][2 * g + 1], ah[mt], &bh[g][2]);
                mma_f16(acc[mt][2 * g],     ah[mt], &bl[g][0]);
                mma_f16(acc[mt][2 * g + 1], ah[mt], &bl[g][2]);
            }
    }
}
// c2 bf16 3-term (unchanged)
__device__ __forceinline__ void mma_panel8(uint32_t abase, uint32_t wbh, uint32_t wbl,
                                           int wm, int wn, int lane, float acc[2][4][4]) {
    uint32_t abl = abase + 16384;
#pragma unroll
    for (int ks = 0; ks < 4; ks++) {
        int k0 = ks * 16;
        uint32_t ah[2][4], al[2][4], bh[2][4], bl[2][4];
        ldsm_x4(a_addr(abase, wm * 32, k0, lane), ah[0]);
        ldsm_x4(a_addr(abase, wm * 32 + 16, k0, lane), ah[1]);
        ldsm_x4(a_addr(abl, wm * 32, k0, lane), al[0]);
        ldsm_x4(a_addr(abl, wm * 32 + 16, k0, lane), al[1]);
        ldsm_x4(b_addr(wbh, wn * 32, k0, lane), bh[0]);
        ldsm_x4(b_addr(wbh, wn * 32 + 16, k0, lane), bh[1]);
        ldsm_x4(b_addr(wbl, wn * 32, k0, lane), bl[0]);
        ldsm_x4(b_addr(wbl, wn * 32 + 16, k0, lane), bl[1]);
#pragma unroll
        for (int mt = 0; mt < 2; mt++)
#pragma unroll
            for (int g = 0; g < 2; g++) {
                mma_bf16(acc[mt][2 * g],     ah[mt], &bh[g][0]);
                mma_bf16(acc[mt][2 * g + 1], ah[mt], &bh[g][2]);
                mma_bf16(acc[mt][2 * g],     ah[mt], &bl[g][0]);
                mma_bf16(acc[mt][2 * g + 1], ah[mt], &bl[g][2]);
                mma_bf16(acc[mt][2 * g],     al[mt], &bh[g][0]);
                mma_bf16(acc[mt][2 * g + 1], al[mt], &bh[g][2]);
            }
    }
}

// ---------------- c3 async feeds (256-row panel) ----------------
__device__ __forceinline__ void issue_panel(const unsigned short* __restrict__ sh,
                                            const int* __restrict__ idx,
                                            int tbase, uint32_t abase, int tid) {
    int r = tid >> 1, q = tid & 1;       // r: 0..255, q: half-row (64B)
    int t = tbase + r;
    bool valid = (t < NTRI);
    int gi = valid ? idx[t] : 0;
    int sz = valid ? 16 : 0;
    const char* ph = (const char*)(sh + (size_t)gi * 64) + q * 64;
    int swm = (r & 7) << 4;
    uint32_t row = abase + (uint32_t)r * 128u;
#pragma unroll
    for (int i = 0; i < 4; i++)
        cp16(row + (uint32_t)((q * 64 + i * 16) ^ swm), ph + i * 16, sz);
}
__device__ __forceinline__ void issue_wlo(int p, uint32_t dst, int tid) {
    const char* src = (const char*)g_wbl + p * 16384 + tid * 32;
    cp16(dst + (uint32_t)tid * 32u, src, 16);
    cp16(dst + (uint32_t)tid * 32u + 16u, src + 16, 16);
}

// ---------------- c2 gather ----------------
__device__ __forceinline__ void gather2p(const float* __restrict__ node,
                                         const int* __restrict__ vi,
                                         const int* __restrict__ vj,
                                         int tbase, int tid, float4* v) {
    int r = tid >> 2, q = tid & 3;
    int e = tbase + r;
    if (e < NEDGE) {
        const float4* a = (const float4*)(node + (size_t)vi[e] * 64) + q * 4;
        const float4* b = (const float4*)(node + (size_t)vj[e] * 64) + q * 4;
#pragma unroll
        for (int i = 0; i < 4; i++) {
            float4 x = a[i], y = b[i];
            v[i] = make_float4(x.x * y.x, x.y * y.y, x.z * y.z, x.w * y.w);
        }
    } else {
#pragma unroll
        for (int i = 0; i < 4; i++) v[i] = make_float4(0.f, 0.f, 0.f, 0.f);
    }
}
__device__ __forceinline__ void cvt_store4(const float4* v, char* buf, int tid) {
    int r = tid >> 2, q = tid & 3;
    int swm = (r & 7) << 4;
#pragma unroll
    for (int i = 0; i < 4; i++) {
        uint32_t h0, l0, h1, l1;
        cvt_pair(v[i].x, v[i].y, h0, l0);
        cvt_pair(v[i].z, v[i].w, h1, l1);
        int off = r * 128 + ((q * 32 + i * 8) ^ swm);
        *(uint2*)(buf + off) = make_uint2(h0, h1);
        *(uint2*)(buf + 16384 + off) = make_uint2(l0, l1);
    }
}

// ============================================================================
// K2: c3 linear — fp16 2-term, 256-row tiles, 3-buffer cp.async ring
// ============================================================================
__global__ void __launch_bounds__(512, 1) k_c3mm(const int* __restrict__ ii,
                                                 const int* __restrict__ ij,
                                                 const int* __restrict__ ik,
                                                 const int* __restrict__ iji,
                                                 const int* __restrict__ ikj) {
    extern __shared__ __align__(128) char smal[];
    __shared__ float sred[256];
    const uint32_t sbal = smem_u32(smal);
    const int tid = threadIdx.x, wid = tid >> 5, lane = tid & 31;
    const int wm = wid >> 2, wn = wid & 3;
    {
        const uint4* srch = (const uint4*)g_wbh;
        uint4* dsth = (uint4*)smal;
        for (int i = tid; i < 5120; i += 512) dsth[i] = srch[i];
    }
    if (tid < 256) sred[tid] = 0.0f;
    __syncthreads();

    const int* idxs[5] = {ii, ij, ik, iji, ikj};

#define PREFETCH(G) do {                                                        \
        int _g = (G);                                                           \
        int _m = _g / 5, _p = _g - 5 * _m;                                      \
        int _tb = (blockIdx.x + _m * gridDim.x) * TILE_M3;                      \
        const unsigned short* _sh = (_p < 3) ? g_nodeh : g_edgeh;               \
        uint32_t _buf = (uint32_t)(_g % 3);                                     \
        issue_panel(_sh, idxs[_p], _tb, sbal + SW_A + _buf * 32768u, tid);      \
        issue_wlo(_p, sbal + SW_WL + _buf * 16384u, tid);                       \
        CP_COMMIT();                                                            \
    } while (0)

    PREFETCH(0);
    PREFETCH(1);

    const int lr = lane >> 2, lq = lane & 3;
    int gp = 0;
    for (int tile = blockIdx.x; tile < NT_TILES; tile += gridDim.x) {
        const int tbase = tile * TILE_M3;
        float acc[4][4][4];
#pragma unroll
        for (int mt = 0; mt < 4; mt++)
#pragma unroll
            for (int nt = 0; nt < 4; nt++)
#pragma unroll
                for (int u = 0; u < 4; u++) acc[mt][nt][u] = 0.0f;

#pragma unroll
        for (int p = 0; p < 5; p++, gp++) {
            CP_WAIT1();
            __syncthreads();
            PREFETCH(gp + 2);
            uint32_t buf = (uint32_t)(gp % 3);
            mma_panelD(sbal + SW_A + buf * 32768u,
                       sbal + (uint32_t)p * 16384u,
                       sbal + SW_WL + buf * 16384u, wm, wn, lane, acc);
        }

        // epilogue: y3 (fp16) stores + fused fp32 column stats
#pragma unroll
        for (int mt = 0; mt < 4; mt++) {
            int gr = tbase + wm * 64 + mt * 16 + lr;
#pragma unroll
            for (int nt = 0; nt < 4; nt++) {
                int col = wn * 32 + nt * 8 + lq * 2;
                __half2 v0 = __floats2half2_rn(acc[mt][nt][0], acc[mt][nt][1]);
                __half2 v1 = __floats2half2_rn(acc[mt][nt][2], acc[mt][nt][3]);
                if (gr < NTRI)
                    *(uint32_t*)&g_y3h[(size_t)gr * CC + col] = *(uint32_t*)&v0;
                if (gr + 8 < NTRI)
                    *(uint32_t*)&g_y3h[(size_t)(gr + 8) * CC + col] = *(uint32_t*)&v1;
            }
        }
        float sv[8], qv[8];
#pragma unroll
        for (int nt = 0; nt < 4; nt++)
#pragma unroll
            for (int j = 0; j < 2; j++) {
                float s = 0.0f, q = 0.0f;
#pragma unroll
                for (int mt = 0; mt < 4; mt++) {
                    float a0 = acc[mt][nt][j], a1 = acc[mt][nt][j + 2];
                    s += a0 + a1;
                    q += a0 * a0 + a1 * a1;
                }
                sv[nt * 2 + j] = s;
                qv[nt * 2 + j] = q;
            }
#pragma unroll
        for (int i = 0; i < 8; i++) {
#pragma unroll
            for (int m = 4; m < 32; m <<= 1) {
                sv[i] += __shfl_xor_sync(0xffffffff, sv[i], m);
                qv[i] += __shfl_xor_sync(0xffffffff, qv[i], m);
            }
        }
        if (lane < 4) {
#pragma unroll
            for (int i = 0; i < 8; i++) {
                int col = wn * 32 + (i >> 1) * 8 + lane * 2 + (i & 1);
                atomicAdd(&sred[col], sv[i]);
                atomicAdd(&sred[128 + col], qv[i]);
            }
        }
    }
    __syncthreads();
    if (tid < 256) atomicAdd(&g_sumbuf[256 + tid], sred[tid]);
#undef PREFETCH
}

// ============================================================================
// K1: c2 linear — bf16 3-term, 512 threads, cross-tile double buffer
// ============================================================================
__global__ void __launch_bounds__(512, 1) k_c2mm(const float* __restrict__ node,
                                                 const int* __restrict__ vi,
                                                 const int* __restrict__ vj) {
    extern __shared__ __align__(128) char smal[];
    __shared__ float sred[256];
    const uint32_t sbal = smem_u32(smal);
    const int tid = threadIdx.x, wid = tid >> 5, lane = tid & 31;
    const int wm = wid >> 2, wn = wid & 3;
    {
        const uint4* srch = (const uint4*)g_w2h;
        const uint4* srcl = (const uint4*)g_w2l;
        uint4* dsth = (uint4*)smal;
        uint4* dstl = (uint4*)(smal + 16384);
        for (int i = tid; i < 1024; i += 512) { dsth[i] = srch[i]; dstl[i] = srcl[i]; }
    }
    if (tid < 256) sred[tid] = 0.0f;

    float4 v[4];
    int tile = blockIdx.x;
    if (tile < NE_TILES) {
        gather2p(node, vi, vj, tile * TILE_M, tid, v);
        cvt_store4(v, smal + SW2_A, tid);
    }
    __syncthreads();
    uint32_t parOff = 0;
    const int lr = lane >> 2, lq = lane & 3;

    for (; tile < NE_TILES; tile += gridDim.x) {
        const int tbase = tile * TILE_M;
        float acc[2][4][4];
#pragma unroll
        for (int mt = 0; mt < 2; mt++)
#pragma unroll
            for (int nt = 0; nt < 4; nt++)
#pragma unroll
                for (int u = 0; u < 4; u++) acc[mt][nt][u] = 0.0f;

        int ntile = tile + gridDim.x;
        if (ntile < NE_TILES) gather2p(node, vi, vj, ntile * TILE_M, tid, v);
        mma_panel8(sbal + SW2_A + parOff, sbal, sbal + 16384u, wm, wn, lane, acc);
        if (ntile < NE_TILES) cvt_store4(v, smal + SW2_A + (parOff ^ 32768u), tid);

#pragma unroll
        for (int mt = 0; mt < 2; mt++) {
            int gr = tbase + wm * 32 + mt * 16 + lr;
#pragma unroll
            for (int nt = 0; nt < 4; nt++) {
                int col = wn * 32 + nt * 8 + lq * 2;
                if (gr < NEDGE)
                    *(float2*)&g_y2[(size_t)gr * CC + col] = make_float2(acc[mt][nt][0], acc[mt][nt][1]);
                if (gr + 8 < NEDGE)
                    *(float2*)&g_y2[(size_t)(gr + 8) * CC + col] = make_float2(acc[mt][nt][2], acc[mt][nt][3]);
            }
        }
        float sv[8], qv[8];
#pragma unroll
        for (int nt = 0; nt < 4; nt++)
#pragma unroll
            for (int j = 0; j < 2; j++) {
                float a0 = acc[0][nt][j], a1 = acc[0][nt][j + 2];
                float a2 = acc[1][nt][j], a3 = acc[1][nt][j + 2];
                sv[nt * 2 + j] = a0 + a1 + a2 + a3;
                qv[nt * 2 + j] = a0 * a0 + a1 * a1 + a2 * a2 + a3 * a3;
            }
#pragma unroll
        for (int i = 0; i < 8; i++) {
#pragma unroll
            for (int m = 4; m < 32; m <<= 1) {
                sv[i] += __shfl_xor_sync(0xffffffff, sv[i], m);
                qv[i] += __shfl_xor_sync(0xffffffff, qv[i], m);
            }
        }
        if (lane < 4) {
#pragma unroll
            for (int i = 0; i < 8; i++) {
                int col = wn * 32 + (i >> 1) * 8 + lane * 2 + (i & 1);
                atomicAdd(&sred[col], sv[i]);
                atomicAdd(&sred[128 + col], qv[i]);
            }
        }
        __syncthreads();
        parOff ^= 32768u;
    }
    __syncthreads();
    if (tid < 256) atomicAdd(&g_sumbuf[tid], sred[tid]);
}

// ============================================================================
__global__ void k_stats1(const float* __restrict__ gc2, const float* __restrict__ bc2,
                         const float* __restrict__ gc3, const float* __restrict__ bc3) {
    int tid = threadIdx.x;  // 256
    if (tid < 128) {
        float mean = g_sumbuf[tid] * (1.0f / NEDGE);
        float var  = g_sumbuf[128 + tid] * (1.0f / NEDGE) - mean * mean;
        float a = gc2[tid] * rsqrtf(var + EPSF);
        g_ab[tid] = a;
        g_ab[128 + tid] = bc2[tid] - mean * a;
    } else {
        int c = tid - 128;
        float mean = g_sumbuf[256 + c] * (1.0f / NTRI);
        float var  = g_sumbuf[384 + c] * (1.0f / NTRI) - mean * mean;
        float a = gc3[c] * rsqrtf(var + EPSF);
        g_ab[256 + c] = a;
        g_ab[384 + c] = bc3[c] - mean * a;
    }
}

// ============================================================================
__global__ void __launch_bounds__(256) k_c2act() {
    __shared__ float sred[128];
    int tid = threadIdx.x;
    if (tid < 128) sred[tid] = 0.0f;
    __syncthreads();
    size_t i0 = (size_t)blockIdx.x * 256 + tid;
    int c = (int)(i0 & 15) * 4;
    float4 af = *(const float4*)&g_ab[c];
    float4 bf = *(const float4*)&g_ab[128 + c];
    float4 ac = *(const float4*)&g_ab[64 + c];
    float4 bc = *(const float4*)&g_ab[192 + c];
    float s[4] = {0, 0, 0, 0}, q[4] = {0, 0, 0, 0};
    size_t stride = (size_t)gridDim.x * 256;
    size_t n = (size_t)NEDGE * 16;
    for (size_t idx = i0; idx < n; idx += stride) {
        size_t e = idx >> 4;
        float4 yf = *(const float4*)&g_y2[(e << 7) + c];
        float4 yc = *(const float4*)&g_y2[(e << 7) + 64 + c];
        float4 g;
        g.x = sigmoidf_(yf.x * af.x + bf.x) * tanhf(yc.x * ac.x + bc.x);
        g.y = sigmoidf_(yf.y * af.y + bf.y) * tanhf(yc.y * ac.y + bc.y);
        g.z = sigmoidf_(yf.z * af.z + bf.z) * tanhf(yc.z * ac.z + bc.z);
        g.w = sigmoidf_(yf.w * af.w + bf.w) * tanhf(yc.w * ac.w + bc.w);
        *(float4*)&g_g2[idx << 2] = g;
        s[0] += g.x; s[1] += g.y; s[2] += g.z; s[3] += g.w;
        q[0] += g.x * g.x; q[1] += g.y * g.y; q[2] += g.z * g.z; q[3] += g.w * g.w;
    }
#pragma unroll
    for (int u = 0; u < 4; u++) {
        atomicAdd(&sred[c + u], s[u]);
        atomicAdd(&sred[64 + c + u], q[u]);
    }
    __syncthreads();
    if (tid < 128) atomicAdd(&g_sumbuf[512 + tid], sred[tid]);
}

// ============================================================================
// K5: c3 activation + scatter, reads fp16 y3
// ============================================================================
__global__ void __launch_bounds__(256) k_c3act(const int* __restrict__ iji) {
    size_t i0 = (size_t)blockIdx.x * 256 + threadIdx.x;
    int c = (int)(i0 & 15) * 4;
    float4 af = *(const float4*)&g_ab[256 + c];
    float4 bf = *(const float4*)&g_ab[384 + c];
    float4 ac = *(const float4*)&g_ab[320 + c];
    float4 bc = *(const float4*)&g_ab[448 + c];
    size_t stride = (size_t)gridDim.x * 256;
    size_t n = (size_t)NTRI * 16;
    for (size_t idx = i0; idx < n; idx += stride) {
        size_t t = idx >> 4;
        uint2 pf = *(const uint2*)&g_y3h[(t << 7) + c];
        uint2 pc = *(const uint2*)&g_y3h[(t << 7) + 64 + c];
        float2 f01 = __half22float2(*(__half2*)&pf.x);
        float2 f23 = __half22float2(*(__half2*)&pf.y);
        float2 c01 = __half22float2(*(__half2*)&pc.x);
        float2 c23 = __half22float2(*(__half2*)&pc.y);
        float m0 = sigmoidf_(f01.x * af.x + bf.x) * tanhf(c01.x * ac.x + bc.x);
        float m1 = sigmoidf_(f01.y * af.y + bf.y) * tanhf(c01.y * ac.y + bc.y);
        float m2 = sigmoidf_(f23.x * af.z + bf.z) * tanhf(c23.x * ac.z + bc.z);
        float m3 = sigmoidf_(f23.y * af.w + bf.w) * tanhf(c23.y * ac.w + bc.w);
        float* dst = g_agg + ((size_t)iji[t] << 6) + c;
        asm volatile("red.global.v4.f32.add [%0], {%1, %2, %3, %4};"
                     :: "l"(dst), "f"(m0), "f"(m1), "f"(m2), "f"(m3) : "memory");
    }
}

// ============================================================================
__global__ void __launch_bounds__(256) k_aggstats() {
    __shared__ float sred[128];
    int tid = threadIdx.x;
    if (tid < 128) sred[tid] = 0.0f;
    __syncthreads();
    size_t i0 = (size_t)blockIdx.x * 256 + tid;
    int c = (int)(i0 & 15) * 4;
    float s[4] = {0, 0, 0, 0}, q[4] = {0, 0, 0, 0};
    size_t stride = (size_t)gridDim.x * 256;
    size_t n = (size_t)NEDGE * 16;
    for (size_t idx = i0; idx < n; idx += stride) {
        float4 vv = *(const float4*)&g_agg[idx << 2];
        s[0] += vv.x; s[1] += vv.y; s[2] += vv.z; s[3] += vv.w;
        q[0] += vv.x * vv.x; q[1] += vv.y * vv.y; q[2] += vv.z * vv.z; q[3] += vv.w * vv.w;
    }
#pragma unroll
    for (int u = 0; u < 4; u++) {
        atomicAdd(&sred[c + u], s[u]);
        atomicAdd(&sred[64 + c + u], q[u]);
    }
    __syncthreads();
    if (tid < 128) atomicAdd(&g_sumbuf[640 + tid], sred[tid]);
}

// ============================================================================
__global__ void k_stats2(const float* __restrict__ g22, const float* __restrict__ b22,
                         const float* __restrict__ g32, const float* __restrict__ b32) {
    int tid = threadIdx.x;  // 128
    if (tid < 64) {
        float mean = g_sumbuf[512 + tid] * (1.0f / NEDGE);
        float var  = g_sumbuf[576 + tid] * (1.0f / NEDGE) - mean * mean;
        float a = g22[tid] * rsqrtf(var + EPSF);
        g_ab[512 + tid] = a;
        g_ab[576 + tid] = b22[tid] - mean * a;
    } else {
        int c = tid - 64;
        float mean = g_sumbuf[640 + c] * (1.0f / NEDGE);
        float var  = g_sumbuf[704 + c] * (1.0f / NEDGE) - mean * mean;
        float a = g32[c] * rsqrtf(var + EPSF);
        g_ab[640 + c] = a;
        g_ab[704 + c] = b32[c] - mean * a;
    }
}

// ============================================================================
__global__ void __launch_bounds__(256) k_out(const float* __restrict__ edge,
                                             float* __restrict__ out) {
    size_t i0 = (size_t)blockIdx.x * 256 + threadIdx.x;
    int c = (int)(i0 & 15) * 4;
    float4 a2 = *(const float4*)&g_ab[512 + c];
    float4 b2v = *(const float4*)&g_ab[576 + c];
    float4 a3 = *(const float4*)&g_ab[640 + c];
    float4 b3v = *(const float4*)&g_ab[704 + c];
    size_t stride = (size_t)gridDim.x * 256;
    size_t n = (size_t)NEDGE * 16;
    for (size_t idx = i0; idx < n; idx += stride) {
        float4 e = *(const float4*)&edge[idx << 2];
        float4 g = *(const float4*)&g_g2[idx << 2];
        float4 a = *(const float4*)&g_agg[idx << 2];
        float4 o;
        o.x = tanhf(e.x + g.x * a2.x + b2v.x + a.x * a3.x + b3v.x);
        o.y = tanhf(e.y + g.y * a2.y + b2v.y + a.y * a3.y + b3v.y);
        o.z = tanhf(e.z + g.z * a2.z + b2v.z + a.z * a3.z + b3v.z);
        o.w = tanhf(e.w + g.w * a2.w + b2v.w + a.w * a3.w + b3v.w);
        *(float4*)&out[idx << 2] = o;
    }
}

// ============================================================================
extern "C" void kernel_launch(void* const* d_in, const int* in_sizes, int n_in,
                              void* d_out, int out_size) {
    const float* node = (const float*)d_in[0];
    const float* edge = (const float*)d_in[1];
    const int* vi     = (const int*)d_in[2];
    const int* vj     = (const int*)d_in[3];
    const int* idx_i  = (const int*)d_in[4];
    const int* idx_j  = (const int*)d_in[5];
    const int* idx_k  = (const int*)d_in[6];
    const int* idx_ji = (const int*)d_in[7];
    const int* idx_kj = (const int*)d_in[8];
    const float* W2   = (const float*)d_in[9];
    const float* W3   = (const float*)d_in[11];
    const float* gc2  = (const float*)d_in[13];
    const float* bc2  = (const float*)d_in[14];
    const float* gc3  = (const float*)d_in[15];
    const float* bc3  = (const float*)d_in[16];
    const float* g22  = (const float*)d_in[17];
    const float* b22  = (const float*)d_in[18];
    const float* g32  = (const float*)d_in[19];
    const float* b32  = (const float*)d_in[20];
    float* out = (float*)d_out;

    cudaFuncSetAttribute(k_c2mm, cudaFuncAttributeMaxDynamicSharedMemorySize, SMEM_C2);
    cudaFuncSetAttribute(k_c3mm, cudaFuncAttributeMaxDynamicSharedMemorySize, SMEM_C3);

    k_prep<<<2048, 256>>>(W3, W2, node, edge);
    k_c3mm<<<148, 512, SMEM_C3>>>(idx_i, idx_j, idx_k, idx_ji, idx_kj);
    k_c2mm<<<148, 512, SMEM_C2>>>(node, vi, vj);
    k_stats1<<<1, 256>>>(gc2, bc2, gc3, bc3);
    k_c2act<<<512, 256>>>();
    k_c3act<<<2048, 256>>>(idx_ji);
    k_aggstats<<<512, 256>>>();
    k_stats2<<<1, 128>>>(g22, b22, g32, b32);
    k_out<<<512, 256>>>(edge, out);
}